// round 1
// baseline (speedup 1.0000x reference)
#include <cuda_runtime.h>
#include <cstdint>

#define D      512
#define HEADS  8
#define DH     64
#define NB     4
#define TQ     512
#define TS     512
#define VOCABSZ 32000
#define ROWS   (NB*TQ)   // 2048

// ---------------- scratch (__device__ globals; no allocation allowed) ----------------
__device__ float g_WfcQT[D*D];          // WfcQ transposed (1 MB)
__device__ float g_Wc[D*D];             // folded Wq@WfcQ   (1 MB)
__device__ float g_bc[D];
__device__ float g_QK[2*ROWS*D];        // Q rows [0,2048), K rows [2048,4096)  (8 MB)
__device__ float g_scores[NB*HEADS*TQ*TS]; // 33.5 MB
__device__ float g_attn[NB*TQ*TS];      // 4 MB, head-averaged attention
__device__ int   g_gid[NB*TS];          // group id of each src position
__device__ int   g_gtok[NB*TS];         // token of each group
__device__ int   g_ng[NB];              // number of groups per batch

// ---------------- f32x2 packed-FMA helpers ----------------
__device__ __forceinline__ unsigned long long pack2s(float x){
    unsigned long long r; unsigned u = __float_as_uint(x);
    asm("mov.b64 %0, {%1, %1};" : "=l"(r) : "r"(u));
    return r;
}
__device__ __forceinline__ unsigned long long pack2f(float x, float y){
    unsigned long long r;
    asm("mov.b64 %0, {%1, %2};" : "=l"(r) : "r"(__float_as_uint(x)), "r"(__float_as_uint(y)));
    return r;
}
__device__ __forceinline__ void ffma2(unsigned long long& d, unsigned long long a, unsigned long long b){
    asm("fma.rn.f32x2 %0, %1, %2, %0;" : "+l"(d) : "l"(a), "l"(b));
}
__device__ __forceinline__ float2 unpack2(unsigned long long v){
    unsigned lo, hi;
    asm("mov.b64 {%0, %1}, %2;" : "=r"(lo), "=r"(hi) : "l"(v));
    return make_float2(__uint_as_float(lo), __uint_as_float(hi));
}

// ---------------- NT GEMM, 128x128 tile, 256 threads, 8x8 micro (split 4+4) ----------------
// C[m,n] = alpha * sum_k A[m,k]*B[n,k]  (+ bias[n])
template<bool BIAS>
__device__ __forceinline__ void gemm_nt_128(
    const float* __restrict__ A, int lda,
    const float* __restrict__ B, int ldb,
    float* __restrict__ C, int ldc,
    int Kdim, const float* __restrict__ bias, float alpha)
{
    __shared__ float As[8][132];
    __shared__ float Bs[8][132];
    const int tid = threadIdx.x;
    const int tx = tid & 15;
    const int ty = tid >> 4;
    const int m0 = blockIdx.y * 128;
    const int n0 = blockIdx.x * 128;

    unsigned long long acc[8][4];
#pragma unroll
    for (int i=0;i<8;i++)
#pragma unroll
        for (int j=0;j<4;j++) acc[i][j] = 0ULL;

    const int lrow = tid >> 1;        // 0..127
    const int lseg = (tid & 1) * 4;   // 0 or 4
    const float* Ap = A + (size_t)(m0 + lrow) * lda + lseg;
    const float* Bp = B + (size_t)(n0 + lrow) * ldb + lseg;

    for (int k0 = 0; k0 < Kdim; k0 += 8){
        float4 av = *(const float4*)(Ap + k0);
        float4 bv = *(const float4*)(Bp + k0);
        As[lseg+0][lrow]=av.x; As[lseg+1][lrow]=av.y; As[lseg+2][lrow]=av.z; As[lseg+3][lrow]=av.w;
        Bs[lseg+0][lrow]=bv.x; Bs[lseg+1][lrow]=bv.y; Bs[lseg+2][lrow]=bv.z; Bs[lseg+3][lrow]=bv.w;
        __syncthreads();
#pragma unroll
        for (int kk=0; kk<8; kk++){
            float4 a0 = *(const float4*)&As[kk][ty*4];
            float4 a1 = *(const float4*)&As[kk][64 + ty*4];
            float4 b0 = *(const float4*)&Bs[kk][tx*4];
            float4 b1 = *(const float4*)&Bs[kk][64 + tx*4];
            unsigned long long bb0 = pack2f(b0.x,b0.y), bb1 = pack2f(b0.z,b0.w);
            unsigned long long bb2 = pack2f(b1.x,b1.y), bb3 = pack2f(b1.z,b1.w);
            float ar[8] = {a0.x,a0.y,a0.z,a0.w,a1.x,a1.y,a1.z,a1.w};
#pragma unroll
            for (int i=0;i<8;i++){
                unsigned long long aa = pack2s(ar[i]);
                ffma2(acc[i][0], aa, bb0);
                ffma2(acc[i][1], aa, bb1);
                ffma2(acc[i][2], aa, bb2);
                ffma2(acc[i][3], aa, bb3);
            }
        }
        __syncthreads();
    }

#pragma unroll
    for (int ih=0; ih<2; ih++){
#pragma unroll
        for (int ii=0; ii<4; ii++){
            const int i = ih*4 + ii;
            float* crow = C + (size_t)(m0 + ih*64 + ty*4 + ii) * ldc + n0;
#pragma unroll
            for (int jh=0; jh<2; jh++){
                float2 p0 = unpack2(acc[i][jh*2+0]);
                float2 p1 = unpack2(acc[i][jh*2+1]);
                float4 v = make_float4(p0.x*alpha, p0.y*alpha, p1.x*alpha, p1.y*alpha);
                if (BIAS){
                    const float* bp = bias + n0 + jh*64 + tx*4;
                    v.x += bp[0]; v.y += bp[1]; v.z += bp[2]; v.w += bp[3];
                }
                *(float4*)(crow + jh*64 + tx*4) = v;
            }
        }
    }
}

// ---------------- NT GEMM, 64x64 tile (for the small 512^3 weight fold) ----------------
__device__ __forceinline__ void gemm_nt_64(
    const float* __restrict__ A, const float* __restrict__ B, float* __restrict__ C)
{
    __shared__ float As[8][68];
    __shared__ float Bs[8][68];
    const int tid = threadIdx.x;
    const int tx = tid & 15;
    const int ty = tid >> 4;
    const int m0 = blockIdx.y * 64;
    const int n0 = blockIdx.x * 64;

    unsigned long long acc[4][2];
#pragma unroll
    for (int i=0;i<4;i++){ acc[i][0]=0ULL; acc[i][1]=0ULL; }

    const int lrow = tid >> 2;        // 0..63
    const int lseg = (tid & 3) * 2;   // 0,2,4,6
    const float* Ap = A + (size_t)(m0 + lrow) * 512 + lseg;
    const float* Bp = B + (size_t)(n0 + lrow) * 512 + lseg;

    for (int k0 = 0; k0 < 512; k0 += 8){
        float2 av = *(const float2*)(Ap + k0);
        float2 bv = *(const float2*)(Bp + k0);
        As[lseg+0][lrow]=av.x; As[lseg+1][lrow]=av.y;
        Bs[lseg+0][lrow]=bv.x; Bs[lseg+1][lrow]=bv.y;
        __syncthreads();
#pragma unroll
        for (int kk=0; kk<8; kk++){
            float4 a = *(const float4*)&As[kk][ty*4];
            float4 b = *(const float4*)&Bs[kk][tx*4];
            unsigned long long bb0 = pack2f(b.x,b.y), bb1 = pack2f(b.z,b.w);
            float ar[4] = {a.x,a.y,a.z,a.w};
#pragma unroll
            for (int i=0;i<4;i++){
                unsigned long long aa = pack2s(ar[i]);
                ffma2(acc[i][0], aa, bb0);
                ffma2(acc[i][1], aa, bb1);
            }
        }
        __syncthreads();
    }
#pragma unroll
    for (int i=0;i<4;i++){
        float2 p0 = unpack2(acc[i][0]);
        float2 p1 = unpack2(acc[i][1]);
        *(float4*)(C + (size_t)(m0 + ty*4 + i)*512 + n0 + tx*4) =
            make_float4(p0.x, p0.y, p1.x, p1.y);
    }
}

// ---------------- kernels ----------------

// transpose WfcQ -> g_WfcQT   (grid 16x16, block 32x8)
__global__ void k_transpose(const float* __restrict__ W){
    __shared__ float t[32][33];
    int x  = blockIdx.x*32 + threadIdx.x;
    int y0 = blockIdx.y*32 + threadIdx.y;
#pragma unroll
    for (int i=0;i<32;i+=8) t[threadIdx.y+i][threadIdx.x] = W[(size_t)(y0+i)*D + x];
    __syncthreads();
    int orow = blockIdx.x*32 + threadIdx.y;
    int ocol = blockIdx.y*32 + threadIdx.x;
#pragma unroll
    for (int i=0;i<32;i+=8) g_WfcQT[(size_t)(orow+i)*D + ocol] = t[threadIdx.x][threadIdx.y+i];
}

// bc = Wq @ bfcQ + bq    (grid 512 blocks x 128 threads)
__global__ void k_bc(const float* __restrict__ Wq, const float* __restrict__ bfcQ,
                     const float* __restrict__ bq){
    __shared__ float red[128];
    int i = blockIdx.x, t = threadIdx.x;
    float s = 0.f;
    for (int k = t; k < D; k += 128) s += Wq[(size_t)i*D + k] * bfcQ[k];
    red[t] = s; __syncthreads();
    for (int o = 64; o > 0; o >>= 1){ if (t < o) red[t] += red[t+o]; __syncthreads(); }
    if (t == 0) g_bc[i] = red[0] + bq[i];
}

// Wc = Wq @ WfcQ  == NT(Wq, WfcQ^T)     (grid 8x8, 256 threads)
__global__ void k_fold(const float* __restrict__ Wq){
    gemm_nt_64(Wq, g_WfcQT, g_Wc);
}

// z=0: Q = dec@Wc^T + bc ; z=1: K = enc@Wk^T + bk   (grid 4x16x2, 256 threads)
__global__ void k_proj(const float* __restrict__ dec, const float* __restrict__ enc,
                       const float* __restrict__ Wk, const float* __restrict__ bk){
    if (blockIdx.z == 0)
        gemm_nt_128<true>(dec, D, g_Wc, D, g_QK, D, D, g_bc, 1.0f);
    else
        gemm_nt_128<true>(enc, D, Wk, D, g_QK + (size_t)ROWS*D, D, D, bk, 1.0f);
}

// scores[b,h] = (1/8) * Qh @ Kh^T       (grid 4x4x32, 256 threads)
__global__ void k_scores(){
    int z = blockIdx.z, b = z >> 3, h = z & 7;
    const float* A = g_QK + (size_t)(b*TQ)*D + h*DH;
    const float* B = g_QK + (size_t)(ROWS + b*TS)*D + h*DH;
    float* C = g_scores + (size_t)z*TQ*TS;
    gemm_nt_128<false>(A, D, B, D, C, TS, DH, nullptr, 0.125f);
}

// softmax over ts per (b,h,q) + mean over heads -> g_attn   (grid 2048, 256 threads)
__global__ void k_softmax(){
    int bq = blockIdx.x, b = bq >> 9, q = bq & 511;
    int t = threadIdx.x;
    __shared__ float red[256];
    float acc0 = 0.f, acc1 = 0.f;
    for (int h = 0; h < HEADS; h++){
        const float* row = g_scores + ((size_t)(b*HEADS + h)*TQ + q) * TS;
        float v0 = row[t], v1 = row[t+256];
        red[t] = fmaxf(v0, v1); __syncthreads();
        for (int s = 128; s > 0; s >>= 1){ if (t < s) red[t] = fmaxf(red[t], red[t+s]); __syncthreads(); }
        float m = red[0]; __syncthreads();
        float e0 = __expf(v0 - m), e1 = __expf(v1 - m);
        red[t] = e0 + e1; __syncthreads();
        for (int s = 128; s > 0; s >>= 1){ if (t < s) red[t] += red[t+s]; __syncthreads(); }
        float inv = 1.0f / (8.0f * red[0]); __syncthreads();
        acc0 += e0 * inv; acc1 += e1 * inv;
    }
    float* arow = g_attn + (size_t)bq * TS;
    arow[t] = acc0; arow[t+256] = acc1;
}

// per-batch grouping of src tokens (grid 4 blocks x 512 threads)
__global__ void k_groups(const int* __restrict__ src){
    __shared__ int stok[512];
    __shared__ int sfirst[512];
    __shared__ int sgarr[512];
    __shared__ int sG;
    int b = blockIdx.x, j = threadIdx.x;
    stok[j] = src[b*TS + j];
    __syncthreads();
    int tj = stok[j];
    int f = 0;
    while (stok[f] != tj) f++;       // terminates at f<=j
    sfirst[j] = f;
    __syncthreads();
    if (j == 0){
        int run = 0;
        for (int i = 0; i < 512; i++){
            sgarr[i] = run;
            if (sfirst[i] == i) run++;
        }
        sG = run;
    }
    __syncthreads();
    int g = sgarr[sfirst[j]];
    g_gid[b*TS + j] = g;
    if (sfirst[j] == j) g_gtok[b*TS + g] = tj;
    if (j == 0) g_ng[b] = sG;
}

// final: out = w*softmax(a_output)/ + (1-w)*p1, streaming + sparse fixups
// grid 2048 (b,q), 256 threads
__global__ void k_final(const float* __restrict__ dec, const float* __restrict__ p1,
                        const float* __restrict__ Wfcw, const float* __restrict__ bfcw,
                        float* __restrict__ out){
    int bq = blockIdx.x, b = bq >> 9;
    int t = threadIdx.x;
    __shared__ float gsum[512];
    __shared__ float red[256];
    __shared__ float s_w, s_Z;

    gsum[t] = 0.f; gsum[t+256] = 0.f;
    __syncthreads();

    const float* arow = g_attn + (size_t)bq * TS;
    const int* gidb = g_gid + b*TS;
    atomicAdd(&gsum[gidb[t]],     arow[t]);
    atomicAdd(&gsum[gidb[t+256]], arow[t+256]);

    // gate w = sigmoid(dec_row . Wfcw + bfcw)
    const float* drow = dec + (size_t)bq * D;
    float pw = drow[t]*Wfcw[t] + drow[t+256]*Wfcw[t+256];
    red[t] = pw; __syncthreads();   // also fences the atomics
    for (int s = 128; s > 0; s >>= 1){ if (t < s) red[t] += red[t+s]; __syncthreads(); }
    if (t == 0) s_w = 1.0f / (1.0f + __expf(-(red[0] + bfcw[0])));
    __syncthreads();

    // Z = (VOCAB - G) + sum_g exp(s_g); also overwrite gsum[g] with exp(s_g)
    int G = g_ng[b];
    float pz = 0.f;
    for (int g = t; g < G; g += 256){ float e = __expf(gsum[g]); gsum[g] = e; pz += e; }
    red[t] = pz; __syncthreads();
    for (int s = 128; s > 0; s >>= 1){ if (t < s) red[t] += red[t+s]; __syncthreads(); }
    if (t == 0) s_Z = (float)(VOCABSZ - G) + red[0];
    __syncthreads();

    float w = s_w, Z = s_Z;
    float cw = 1.0f - w;
    float wz = w / Z;               // value for absent tokens: w*exp(0)/Z

    const float4* p14 = (const float4*)(p1 + (size_t)bq * VOCABSZ);
    float4* o4 = (float4*)(out + (size_t)bq * VOCABSZ);
#pragma unroll 4
    for (int i = t; i < VOCABSZ/4; i += 256){
        float4 v = p14[i];
        float4 r;
        r.x = wz + cw * v.x;
        r.y = wz + cw * v.y;
        r.z = wz + cw * v.z;
        r.w = wz + cw * v.w;
        o4[i] = r;
    }
    __syncthreads();   // order bulk stores before fixups to the same addresses

    const int* gtokb = g_gtok + b*TS;
    const float* p1r = p1 + (size_t)bq * VOCABSZ;
    float* outr = out + (size_t)bq * VOCABSZ;
    for (int g = t; g < G; g += 256){
        int v = gtokb[g];
        outr[v] = wz * gsum[g] + cw * p1r[v];
    }
}

// ---------------- launch ----------------
extern "C" void kernel_launch(void* const* d_in, const int* in_sizes, int n_in,
                              void* d_out, int out_size){
    // metadata order: [src_vocab_size?], dec, enc, src, p1, WfcQ, bfcQ, Wq, bq, Wk, bk, Wfcw, bfcw
    int off = (in_sizes[0] == 1) ? 1 : 0;
    const float* dec  = (const float*)d_in[off + 0];
    const float* enc  = (const float*)d_in[off + 1];
    const int*   src  = (const int*)  d_in[off + 2];
    const float* p1   = (const float*)d_in[off + 3];
    const float* WfcQ = (const float*)d_in[off + 4];
    const float* bfcQ = (const float*)d_in[off + 5];
    const float* Wq   = (const float*)d_in[off + 6];
    const float* bq   = (const float*)d_in[off + 7];
    const float* Wk   = (const float*)d_in[off + 8];
    const float* bk   = (const float*)d_in[off + 9];
    const float* Wfcw = (const float*)d_in[off + 10];
    const float* bfcw = (const float*)d_in[off + 11];
    float* out = (float*)d_out;

    k_groups   <<<NB, 512>>>(src);
    k_transpose<<<dim3(16,16), dim3(32,8)>>>(WfcQ);
    k_bc       <<<D, 128>>>(Wq, bfcQ, bq);
    k_fold     <<<dim3(8,8), 256>>>(Wq);
    k_proj     <<<dim3(4,16,2), 256>>>(dec, enc, Wk, bk);
    k_scores   <<<dim3(4,4,32), 256>>>();
    k_softmax  <<<NB*TQ, 256>>>();
    k_final    <<<NB*TQ, 256>>>(dec, p1, Wfcw, bfcw, out);
}

// round 3
// speedup vs baseline: 1.2167x; 1.2167x over previous
#include <cuda_runtime.h>
#include <cstdint>

#define D       512
#define HEADS   8
#define DH      64
#define NB      4
#define TQ      512
#define TS      512
#define VOCABSZ 32000
#define ROWS    (NB*TQ)          // 2048
#define NBMPW   (VOCABSZ/32)     // 1000 bitmap words per batch

typedef unsigned long long ull;

// ---------------- scratch ----------------
__device__ float g_Wc[D*D];                 // folded Wq@WfcQ
__device__ float g_bc[D];
__device__ float g_QK[2*ROWS*D];            // Q rows [0,2048), K rows [2048,4096)
__device__ float g_scores[NB*HEADS*TQ*TS];  // 33.5 MB (L2-resident)
__device__ int   g_gid[NB*TS];              // group id per src position
__device__ int   g_ng[NB];                  // #groups per batch
__device__ int   g_tokmap[NB*VOCABSZ];      // token -> group (valid only where bitmap set)
__device__ unsigned g_bmp[NB*NBMPW];        // vocab presence bitmap
__device__ float g_gval[ROWS*TS];           // per (b,q): wz*exp(gsum_g)
__device__ float g_wz[ROWS];
__device__ float g_cw[ROWS];

// ---------------- f32x2 helpers ----------------
__device__ __forceinline__ ull pack2s(float x){
    ull r; asm("mov.b64 %0, {%1, %1};" : "=l"(r) : "r"(__float_as_uint(x))); return r;
}
__device__ __forceinline__ ull pack2f(float x, float y){
    ull r; asm("mov.b64 %0, {%1, %2};" : "=l"(r) : "r"(__float_as_uint(x)), "r"(__float_as_uint(y))); return r;
}
__device__ __forceinline__ void ffma2(ull& d, ull a, ull b){
    asm("fma.rn.f32x2 %0, %1, %2, %0;" : "+l"(d) : "l"(a), "l"(b));
}
__device__ __forceinline__ float2 unpack2(ull v){
    unsigned lo, hi; asm("mov.b64 {%0, %1}, %2;" : "=r"(lo), "=r"(hi) : "l"(v));
    return make_float2(__uint_as_float(lo), __uint_as_float(hi));
}

// ---------------- unified NT GEMM: 128x64 tile, 256 threads, KC=16, double-buffered ----
// C[m0+0..127, n0+0..63] = alpha * A[m,:Kdim] . B[n,:Kdim]  (+ bias[n])
template<bool BIAS>
__device__ __forceinline__ void gemm_nt_128x64(
    const float* __restrict__ A, int lda,
    const float* __restrict__ B, int ldb,
    float* __restrict__ C, int ldc,
    int Kdim, const float* __restrict__ bias, float alpha,
    int m0, int n0)
{
    __shared__ float As[2][16][132];
    __shared__ float Bs[2][16][68];
    const int t  = threadIdx.x;
    const int tx = t & 15;          // n micro: cols tx*4..+3
    const int ty = t >> 4;          // m micro: rows ty*4..+3 (+64)

    ull acc[4][4];                  // 4 m-pairs x 4 n
#pragma unroll
    for (int i=0;i<4;i++)
#pragma unroll
        for (int j=0;j<4;j++) acc[i][j] = 0ULL;

    const int arow = t >> 2;        // 0..63 (second A item = +64)
    const int ac4  = t & 3;         // k-float4 column within chunk
    const int brow = t >> 2;        // 0..63
    const int bc4  = t & 3;

    const float* Apl = A + (size_t)(m0 + arow) * lda + ac4*4;
    const float* Aph = A + (size_t)(m0 + arow + 64) * lda + ac4*4;
    const float* Bp  = B + (size_t)(n0 + brow) * ldb + bc4*4;

    float4 pa0, pa1, pb;
    const int nch = Kdim >> 4;

    // prologue: chunk 0
    pa0 = *(const float4*)(Apl);
    pa1 = *(const float4*)(Aph);
    pb  = *(const float4*)(Bp);
    {
        const int kb = ac4*4;
        As[0][kb+0][arow]=pa0.x; As[0][kb+1][arow]=pa0.y; As[0][kb+2][arow]=pa0.z; As[0][kb+3][arow]=pa0.w;
        As[0][kb+0][arow+64]=pa1.x; As[0][kb+1][arow+64]=pa1.y; As[0][kb+2][arow+64]=pa1.z; As[0][kb+3][arow+64]=pa1.w;
        const int kbb = bc4*4;
        Bs[0][kbb+0][brow]=pb.x; Bs[0][kbb+1][brow]=pb.y; Bs[0][kbb+2][brow]=pb.z; Bs[0][kbb+3][brow]=pb.w;
    }
    __syncthreads();

    for (int c = 0; c < nch; c++){
        if (c+1 < nch){
            const int c0 = (c+1) << 4;
            pa0 = *(const float4*)(Apl + c0);
            pa1 = *(const float4*)(Aph + c0);
            pb  = *(const float4*)(Bp  + c0);
        }
        const int buf = c & 1;
#pragma unroll
        for (int kk = 0; kk < 16; kk++){
            float4 a0 = *(const float4*)&As[buf][kk][ty*4];
            float4 a1 = *(const float4*)&As[buf][kk][64 + ty*4];
            float4 b  = *(const float4*)&Bs[buf][kk][tx*4];
            ull A0 = pack2f(a0.x, a0.y), A1 = pack2f(a0.z, a0.w);
            ull A2 = pack2f(a1.x, a1.y), A3 = pack2f(a1.z, a1.w);
            ull b0 = pack2s(b.x), b1 = pack2s(b.y), b2 = pack2s(b.z), b3 = pack2s(b.w);
            ffma2(acc[0][0], A0, b0); ffma2(acc[0][1], A0, b1); ffma2(acc[0][2], A0, b2); ffma2(acc[0][3], A0, b3);
            ffma2(acc[1][0], A1, b0); ffma2(acc[1][1], A1, b1); ffma2(acc[1][2], A1, b2); ffma2(acc[1][3], A1, b3);
            ffma2(acc[2][0], A2, b0); ffma2(acc[2][1], A2, b1); ffma2(acc[2][2], A2, b2); ffma2(acc[2][3], A2, b3);
            ffma2(acc[3][0], A3, b0); ffma2(acc[3][1], A3, b1); ffma2(acc[3][2], A3, b2); ffma2(acc[3][3], A3, b3);
        }
        if (c+1 < nch){
            const int nb = (c+1) & 1;
            const int kb = ac4*4;
            As[nb][kb+0][arow]=pa0.x; As[nb][kb+1][arow]=pa0.y; As[nb][kb+2][arow]=pa0.z; As[nb][kb+3][arow]=pa0.w;
            As[nb][kb+0][arow+64]=pa1.x; As[nb][kb+1][arow+64]=pa1.y; As[nb][kb+2][arow+64]=pa1.z; As[nb][kb+3][arow+64]=pa1.w;
            const int kbb = bc4*4;
            Bs[nb][kbb+0][brow]=pb.x; Bs[nb][kbb+1][brow]=pb.y; Bs[nb][kbb+2][brow]=pb.z; Bs[nb][kbb+3][brow]=pb.w;
        }
        __syncthreads();
    }

    float4 bv = make_float4(0.f,0.f,0.f,0.f);
    if (BIAS) bv = *(const float4*)(bias + n0 + tx*4);
#pragma unroll
    for (int i=0;i<4;i++){
        const int rbase = m0 + (i>>1)*64 + ty*4 + (i&1)*2;
        float2 u0 = unpack2(acc[i][0]), u1 = unpack2(acc[i][1]);
        float2 u2 = unpack2(acc[i][2]), u3 = unpack2(acc[i][3]);
        float4 lo = make_float4(u0.x*alpha + bv.x, u1.x*alpha + bv.y, u2.x*alpha + bv.z, u3.x*alpha + bv.w);
        float4 hi = make_float4(u0.y*alpha + bv.x, u1.y*alpha + bv.y, u2.y*alpha + bv.z, u3.y*alpha + bv.w);
        *(float4*)(C + (size_t)rbase*ldc + n0 + tx*4) = lo;
        *(float4*)(C + (size_t)(rbase+1)*ldc + n0 + tx*4) = hi;
    }
}

// ---------------- kernels ----------------

// setup: blocks 0..3 = per-batch grouping + bitmap + tokmap; blocks 4..19 = bc rows
__global__ void k_setup(const int* __restrict__ src, const float* __restrict__ Wq,
                        const float* __restrict__ bfcQ, const float* __restrict__ bq){
    const int blk = blockIdx.x, t = threadIdx.x;
    if (blk < NB){
        const int b = blk;
        __shared__ int stok[512];
        __shared__ int sfirst[512];
        __shared__ int sgarr[512];
        __shared__ unsigned sbmp[NBMPW];
        stok[t]     = src[b*TS + t];
        stok[t+256] = src[b*TS + t + 256];
        for (int i = t; i < NBMPW; i += 256) sbmp[i] = 0u;
        __syncthreads();
        for (int jj = t; jj < 512; jj += 256){
            int tok = stok[jj]; int f = 0;
            while (stok[f] != tok) f++;
            sfirst[jj] = f;
        }
        __syncthreads();
        if (t == 0){
            int run = 0;
            for (int i = 0; i < 512; i++){ sgarr[i] = run; if (sfirst[i] == i) run++; }
            g_ng[b] = run;
        }
        __syncthreads();
        for (int jj = t; jj < 512; jj += 256){
            int f = sfirst[jj], g = sgarr[f];
            g_gid[b*TS + jj] = g;
            if (f == jj){
                int tok = stok[jj];
                g_tokmap[b*VOCABSZ + tok] = g;
                atomicOr(&sbmp[tok >> 5], 1u << (tok & 31));
            }
        }
        __syncthreads();
        for (int i = t; i < NBMPW; i += 256) g_bmp[b*NBMPW + i] = sbmp[i];
    } else {
        // bc[row] = Wq[row,:] . bfcQ + bq[row]
        const int row = (blk - NB)*32 + (t >> 3);
        const int l8 = t & 7;
        float s = 0.f;
        for (int k = l8; k < D; k += 8) s += Wq[(size_t)row*D + k] * bfcQ[k];
        s += __shfl_down_sync(0xFFFFFFFFu, s, 4, 8);
        s += __shfl_down_sync(0xFFFFFFFFu, s, 2, 8);
        s += __shfl_down_sync(0xFFFFFFFFu, s, 1, 8);
        if (l8 == 0) g_bc[row] = s + bq[row];
    }
}

// Wc = Wq @ WfcQ (NN), 32x32 tiles, grid (16,16), 256 threads
__global__ void k_fold(const float* __restrict__ Wq, const float* __restrict__ WfcQ){
    __shared__ float As[32][34];
    __shared__ float Bs[32][34];
    const int t = threadIdx.x;
    const int tx = t & 15, ty = t >> 4;
    const int m0 = blockIdx.y*32, n0 = blockIdx.x*32;
    ull acc0 = 0ULL, acc1 = 0ULL;
    const int lrow = t >> 3, lc4 = t & 7;
    for (int c0 = 0; c0 < D; c0 += 32){
        float4 av = *(const float4*)(Wq   + (size_t)(m0 + lrow)*D + c0 + lc4*4);
        float4 bv = *(const float4*)(WfcQ + (size_t)(c0 + lrow)*D + n0 + lc4*4);
        __syncthreads();
        const int kb = lc4*4;
        As[kb+0][lrow]=av.x; As[kb+1][lrow]=av.y; As[kb+2][lrow]=av.z; As[kb+3][lrow]=av.w;
        Bs[lrow][kb+0]=bv.x; Bs[lrow][kb+1]=bv.y; Bs[lrow][kb+2]=bv.z; Bs[lrow][kb+3]=bv.w;
        __syncthreads();
#pragma unroll
        for (int kk = 0; kk < 32; kk++){
            float2 a = *(const float2*)&As[kk][ty*2];
            float2 b = *(const float2*)&Bs[kk][tx*2];
            ull ap = pack2f(a.x, a.y);
            ffma2(acc0, ap, pack2s(b.x));
            ffma2(acc1, ap, pack2s(b.y));
        }
    }
    float2 u0 = unpack2(acc0), u1 = unpack2(acc1);
    const int r0 = m0 + ty*2, cc = n0 + tx*2;
    g_Wc[(size_t)r0*D + cc]     = u0.x; g_Wc[(size_t)r0*D + cc + 1]     = u1.x;
    g_Wc[(size_t)(r0+1)*D + cc] = u0.y; g_Wc[(size_t)(r0+1)*D + cc + 1] = u1.y;
}

// z=0: Q = dec@Wc^T + bc ; z=1: K = enc@Wk^T + bk ;  grid (8,16,2), 256 thr
__global__ void k_proj(const float* __restrict__ dec, const float* __restrict__ enc,
                       const float* __restrict__ Wk, const float* __restrict__ bk){
    const int m0 = blockIdx.y*128, n0 = blockIdx.x*64;
    if (blockIdx.z == 0)
        gemm_nt_128x64<true>(dec, D, g_Wc, D, g_QK, D, D, g_bc, 1.0f, m0, n0);
    else
        gemm_nt_128x64<true>(enc, D, Wk, D, g_QK + (size_t)ROWS*D, D, D, bk, 1.0f, m0, n0);
}

// scores[b,h] = (1/8) Qh @ Kh^T ; grid (8,4,32), 256 thr
__global__ void k_scores(){
    const int z = blockIdx.z, b = z >> 3, h = z & 7;
    const float* A = g_QK + (size_t)(b*TQ)*D + h*DH;
    const float* B = g_QK + (size_t)(ROWS + b*TS)*D + h*DH;
    float* C = g_scores + (size_t)z*TQ*TS;
    gemm_nt_128x64<false>(A, D, B, D, C, TS, DH, nullptr, 0.125f, blockIdx.y*128, blockIdx.x*64);
}

// per (b,q): softmax over ts for 8 heads, head-mean, group-sum, gate w, Z, outputs
__global__ void k_attn(const float* __restrict__ dec, const float* __restrict__ Wfcw,
                       const float* __restrict__ bfcw){
    const int bq = blockIdx.x, b = bq >> 9, q = bq & 511;
    const int t = threadIdx.x, lane = t & 31, wid = t >> 5;
    __shared__ float sred[16];
    __shared__ float gsum[512];
    gsum[t] = 0.f; gsum[t+256] = 0.f;

    float acc0 = 0.f, acc1 = 0.f;
    const float* base = g_scores + ((size_t)(b*HEADS)*TQ + q) * TS;
#pragma unroll
    for (int h = 0; h < HEADS; h++){
        const float* row = base + (size_t)h * TQ * TS;
        float v0 = row[t], v1 = row[t+256];
        float m = fmaxf(v0, v1);
#pragma unroll
        for (int o = 16; o > 0; o >>= 1) m = fmaxf(m, __shfl_xor_sync(0xFFFFFFFFu, m, o));
        if (lane == 0) sred[wid] = m;
        __syncthreads();
        m = sred[0];
#pragma unroll
        for (int i = 1; i < 8; i++) m = fmaxf(m, sred[i]);
        float e0 = __expf(v0 - m), e1 = __expf(v1 - m);
        float s = e0 + e1;
#pragma unroll
        for (int o = 16; o > 0; o >>= 1) s += __shfl_xor_sync(0xFFFFFFFFu, s, o);
        if (lane == 0) sred[8 + wid] = s;
        __syncthreads();
        float ss = sred[8];
#pragma unroll
        for (int i = 9; i < 16; i++) ss += sred[i];
        float inv = 1.0f / (8.0f * ss);
        acc0 += e0 * inv; acc1 += e1 * inv;
    }

    const int* gidb = g_gid + b*TS;
    atomicAdd(&gsum[gidb[t]],     acc0);
    atomicAdd(&gsum[gidb[t+256]], acc1);

    // gate w
    const float* drow = dec + (size_t)bq * D;
    float pw = drow[t]*Wfcw[t] + drow[t+256]*Wfcw[t+256];
#pragma unroll
    for (int o = 16; o > 0; o >>= 1) pw += __shfl_xor_sync(0xFFFFFFFFu, pw, o);
    if (lane == 0) sred[wid] = pw;
    __syncthreads();                      // also fences the smem atomics
    float wsum = sred[0];
#pragma unroll
    for (int i = 1; i < 8; i++) wsum += sred[i];
    const float w = 1.0f / (1.0f + __expf(-(wsum + bfcw[0])));

    // Z
    const int G = g_ng[b];
    float pz = 0.f;
    for (int g = t; g < G; g += 256){ float e = __expf(gsum[g]); gsum[g] = e; pz += e; }
#pragma unroll
    for (int o = 16; o > 0; o >>= 1) pz += __shfl_xor_sync(0xFFFFFFFFu, pz, o);
    if (lane == 0) sred[8 + wid] = pz;
    __syncthreads();
    float zs = sred[8];
#pragma unroll
    for (int i = 9; i < 16; i++) zs += sred[i];
    const float Z = (float)(VOCABSZ - G) + zs;
    const float wz = w / Z;

    if (t == 0){ g_wz[bq] = wz; g_cw[bq] = 1.0f - w; }
    float* gv = g_gval + (size_t)bq * TS;
    for (int g = t; g < G; g += 256) gv[g] = wz * gsum[g];
}

// final: pure stream out = wz + cw*p1, with inline bitmap fixups. grid 2048 x 512 thr
__global__ void k_final(const float* __restrict__ p1, float* __restrict__ out){
    const int bq = blockIdx.x, b = bq >> 9;
    const int t = threadIdx.x;
    __shared__ unsigned sbmp[NBMPW];
    for (int i = t; i < NBMPW; i += 512) sbmp[i] = g_bmp[b*NBMPW + i];
    const float wz = g_wz[bq], cw = g_cw[bq];
    __syncthreads();

    const float4* p14 = (const float4*)(p1 + (size_t)bq * VOCABSZ);
    float4* o4 = (float4*)(out + (size_t)bq * VOCABSZ);
    const int* tmap = g_tokmap + (size_t)b * VOCABSZ;
    const float* gval = g_gval + (size_t)bq * TS;

#pragma unroll 4
    for (int i = t; i < VOCABSZ/4; i += 512){
        float4 v = p14[i];
        unsigned bits = (sbmp[i >> 3] >> ((i & 7) * 4)) & 0xFu;
        float4 r;
        r.x = fmaf(cw, v.x, wz); r.y = fmaf(cw, v.y, wz);
        r.z = fmaf(cw, v.z, wz); r.w = fmaf(cw, v.w, wz);
        if (bits){
            const int v0 = i * 4;
            if (bits & 1u) r.x = gval[tmap[v0+0]] + cw*v.x;
            if (bits & 2u) r.y = gval[tmap[v0+1]] + cw*v.y;
            if (bits & 4u) r.z = gval[tmap[v0+2]] + cw*v.z;
            if (bits & 8u) r.w = gval[tmap[v0+3]] + cw*v.w;
        }
        o4[i] = r;
    }
}

// ---------------- launch ----------------
extern "C" void kernel_launch(void* const* d_in, const int* in_sizes, int n_in,
                              void* d_out, int out_size){
    int off = (in_sizes[0] == 1) ? 1 : 0;
    const float* dec  = (const float*)d_in[off + 0];
    const float* enc  = (const float*)d_in[off + 1];
    const int*   src  = (const int*)  d_in[off + 2];
    const float* p1   = (const float*)d_in[off + 3];
    const float* WfcQ = (const float*)d_in[off + 4];
    const float* bfcQ = (const float*)d_in[off + 5];
    const float* Wq   = (const float*)d_in[off + 6];
    const float* bq   = (const float*)d_in[off + 7];
    const float* Wk   = (const float*)d_in[off + 8];
    const float* bk   = (const float*)d_in[off + 9];
    const float* Wfcw = (const float*)d_in[off + 10];
    const float* bfcw = (const float*)d_in[off + 11];
    float* out = (float*)d_out;

    k_setup  <<<NB + 16, 256>>>(src, Wq, bfcQ, bq);
    k_fold   <<<dim3(16,16), 256>>>(Wq, WfcQ);
    k_proj   <<<dim3(8,16,2), 256>>>(dec, enc, Wk, bk);
    k_scores <<<dim3(8,4,32), 256>>>();
    k_attn   <<<ROWS, 256>>>(dec, Wfcw, bfcw);
    k_final  <<<ROWS, 512>>>(p1, out);
}

// round 6
// speedup vs baseline: 1.6630x; 1.3668x over previous
#include <cuda_runtime.h>
#include <cuda_bf16.h>
#include <cstdint>

#define D       512
#define HEADS   8
#define DH      64
#define NB      4
#define TQ      512
#define TS      512
#define VOCABSZ 32000
#define ROWS    (NB*TQ)          // 2048
#define NBMPW   (VOCABSZ/32)     // 1000 bitmap words per batch

typedef unsigned long long ull;

// ---------------- scratch ----------------
__device__ float g_bc[D];
__device__ __nv_bfloat16 g_WcB[D*D];         // folded Wq@WfcQ (bf16)
__device__ __nv_bfloat16 g_WkB[D*D];
__device__ __nv_bfloat16 g_decB[ROWS*D];
__device__ __nv_bfloat16 g_encB[ROWS*D];
__device__ __nv_bfloat16 g_QKB[2*ROWS*D];    // Q' (=Q/8) rows [0,2048), K rows [2048,4096)
__device__ float g_scores[NB*HEADS*TQ*TS];   // 33.5 MB
__device__ int   g_gid[NB*TS];
__device__ int   g_ng[NB];
__device__ int   g_tokmap[NB*VOCABSZ];
__device__ unsigned g_bmp[NB*NBMPW];
__device__ float g_gval[ROWS*TS];
__device__ float g_wz[ROWS];
__device__ float g_cw[ROWS];

// ---------------- f32x2 helpers (fold kernel) ----------------
__device__ __forceinline__ ull pack2s(float x){
    ull r; asm("mov.b64 %0, {%1, %1};" : "=l"(r) : "r"(__float_as_uint(x))); return r;
}
__device__ __forceinline__ ull pack2f(float x, float y){
    ull r; asm("mov.b64 %0, {%1, %2};" : "=l"(r) : "r"(__float_as_uint(x)), "r"(__float_as_uint(y))); return r;
}
__device__ __forceinline__ void ffma2(ull& d, ull a, ull b){
    asm("fma.rn.f32x2 %0, %1, %2, %0;" : "+l"(d) : "l"(a), "l"(b));
}
__device__ __forceinline__ float2 unpack2(ull v){
    unsigned lo, hi; asm("mov.b64 {%0, %1}, %2;" : "=r"(lo), "=r"(hi) : "l"(v));
    return make_float2(__uint_as_float(lo), __uint_as_float(hi));
}

// ---------------- HMMA helpers (sm_80-era PTX, valid on compute_103) ----------------
__device__ __forceinline__ uint32_t smem_u32(const void* p){
    uint32_t a;
    asm("{ .reg .u64 t; cvta.to.shared.u64 t, %1; cvt.u32.u64 %0, t; }" : "=r"(a) : "l"(p));
    return a;
}
__device__ __forceinline__ void ldm_x4(uint32_t addr, uint32_t& r0, uint32_t& r1,
                                       uint32_t& r2, uint32_t& r3){
    asm volatile("ldmatrix.sync.aligned.m8n8.x4.shared.b16 {%0,%1,%2,%3}, [%4];"
        : "=r"(r0), "=r"(r1), "=r"(r2), "=r"(r3) : "r"(addr));
}
__device__ __forceinline__ void mma_bf16(float* c, uint32_t a0, uint32_t a1, uint32_t a2,
                                         uint32_t a3, uint32_t b0, uint32_t b1){
    asm volatile("mma.sync.aligned.m16n8k16.row.col.f32.bf16.bf16.f32 "
        "{%0,%1,%2,%3}, {%4,%5,%6,%7}, {%8,%9}, {%0,%1,%2,%3};"
        : "+f"(c[0]), "+f"(c[1]), "+f"(c[2]), "+f"(c[3])
        : "r"(a0), "r"(a1), "r"(a2), "r"(a3), "r"(b0), "r"(b1));
}

// ---- 128x128-tile NT GEMM on HMMA. A,B bf16 row-major [*,K], lda=ldb=512. ----
// C = (A.B^T [+bias]) * alpha ; OUT_BF16: C bf16, else C fp32 (alpha must be 1).
// 256 threads = 8 warps (2 m x 4 n), warp tile 64x32. K = NCHUNK*64.
template<int NCHUNK, bool OUT_BF16>
__device__ __forceinline__ void hgemm_nt(
    const __nv_bfloat16* __restrict__ A, const __nv_bfloat16* __restrict__ B,
    void* __restrict__ Cout, int ldc, const float* __restrict__ bias,
    float alpha, int m0, int n0)
{
    __shared__ __align__(16) uint8_t smA[128*128];   // 128 rows x 64 bf16 (128B), swizzled
    __shared__ __align__(16) uint8_t smB[128*128];
    const int tid = threadIdx.x;
    const int w = tid >> 5, lane = tid & 31;
    const int wm = w >> 2, wn = w & 3;

    float acc[4][4][4];
#pragma unroll
    for (int i=0;i<4;i++)
#pragma unroll
        for (int j=0;j<4;j++)
#pragma unroll
            for (int k=0;k<4;k++) acc[i][j][k] = 0.f;

    // per-lane ldmatrix address components
    const int rowA_l = (lane & 7) + ((lane >> 3) & 1) * 8;  // + wm*64 + fm*16
    const int kbA_l  = lane >> 4;                           // 0/1
    const int rowB_l = (lane & 7) + ((lane >> 4) & 1) * 8;  // + wn*32 + fn*16
    const int kbB_l  = (lane >> 3) & 1;
    const uint32_t sA = smem_u32(smA), sB = smem_u32(smB);

    for (int c = 0; c < NCHUNK; c++){
        // global -> swizzled smem (16B granularity, chunk' = chunk ^ (row&7))
#pragma unroll
        for (int it = 0; it < 4; it++){
            const int i = tid + it*256;        // 0..1023
            const int r = i >> 3, cb = i & 7;
            uint4 va = *(const uint4*)(A + (size_t)(m0 + r)*512 + c*64 + cb*8);
            uint4 vb = *(const uint4*)(B + (size_t)(n0 + r)*512 + c*64 + cb*8);
            const int sw = (cb ^ (r & 7)) << 4;
            *(uint4*)(smA + r*128 + sw) = va;
            *(uint4*)(smB + r*128 + sw) = vb;
        }
        __syncthreads();
#pragma unroll
        for (int ks = 0; ks < 4; ks++){
            uint32_t af[4][4];
#pragma unroll
            for (int fm = 0; fm < 4; fm++){
                const int row = wm*64 + fm*16 + rowA_l;
                const int kb  = ks*2 + kbA_l;
                ldm_x4(sA + row*128 + ((kb ^ (row & 7)) << 4),
                       af[fm][0], af[fm][1], af[fm][2], af[fm][3]);
            }
            uint32_t bf[2][4];
#pragma unroll
            for (int fn = 0; fn < 2; fn++){
                const int row = wn*32 + fn*16 + rowB_l;
                const int kb  = ks*2 + kbB_l;
                ldm_x4(sB + row*128 + ((kb ^ (row & 7)) << 4),
                       bf[fn][0], bf[fn][1], bf[fn][2], bf[fn][3]);
            }
#pragma unroll
            for (int fm = 0; fm < 4; fm++)
#pragma unroll
                for (int j = 0; j < 4; j++)
                    mma_bf16(acc[fm][j], af[fm][0], af[fm][1], af[fm][2], af[fm][3],
                             bf[j>>1][(j&1)*2], bf[j>>1][(j&1)*2 + 1]);
        }
        __syncthreads();
    }

    // epilogue
    const int r_l = lane >> 2, c_l = (lane & 3) * 2;
#pragma unroll
    for (int fm = 0; fm < 4; fm++){
#pragma unroll
        for (int j = 0; j < 4; j++){
            const int row = m0 + wm*64 + fm*16 + r_l;
            const int col = n0 + wn*32 + (j>>1)*16 + (j&1)*8 + c_l;
            const float* a = acc[fm][j];
            if (OUT_BF16){
                __nv_bfloat16* O = (__nv_bfloat16*)Cout;
                const float b0 = bias[col], b1 = bias[col+1];
                *(__nv_bfloat162*)(O + (size_t)row*ldc + col) =
                    __floats2bfloat162_rn((a[0]+b0)*alpha, (a[1]+b1)*alpha);
                *(__nv_bfloat162*)(O + (size_t)(row+8)*ldc + col) =
                    __floats2bfloat162_rn((a[2]+b0)*alpha, (a[3]+b1)*alpha);
            } else {
                float* O = (float*)Cout;
                *(float2*)(O + (size_t)row*ldc + col) = make_float2(a[0], a[1]);
                *(float2*)(O + (size_t)(row+8)*ldc + col) = make_float2(a[2], a[3]);
            }
        }
    }
}

// z=0: Q' = (dec@Wc^T + bc)/8 ; z=1: K = enc@Wk^T + bk.  grid (4,16,2) x 256 thr
__global__ void __launch_bounds__(256) k_proj_h(const float* __restrict__ bk){
    if (blockIdx.z == 0)
        hgemm_nt<8,true>(g_decB, g_WcB, g_QKB, 512, g_bc, 0.125f,
                         blockIdx.y*128, blockIdx.x*128);
    else
        hgemm_nt<8,true>(g_encB, g_WkB, g_QKB + (size_t)ROWS*D, 512, bk, 1.0f,
                         blockIdx.y*128, blockIdx.x*128);
}

// scores[b,h] = Q'h @ Kh^T.  grid (4,4,32) x 256 thr
__global__ void __launch_bounds__(256) k_scores_h(){
    const int z = blockIdx.z, b = z >> 3, h = z & 7;
    hgemm_nt<1,false>(g_QKB + (size_t)(b*TQ)*D + h*DH,
                      g_QKB + (size_t)(ROWS + b*TS)*D + h*DH,
                      g_scores + (size_t)z*TQ*TS, TS, nullptr, 1.0f,
                      blockIdx.y*128, blockIdx.x*128);
}

// ---------------- fp32 -> bf16 conversion (dec, enc, Wk) ----------------
// grid: (2*ROWS*D + D*D)/4 / 256 = 2304 blocks
__global__ void k_tobf16(const float* __restrict__ dec, const float* __restrict__ enc,
                         const float* __restrict__ Wk){
    const int n1 = ROWS*D;
    const int i4 = (blockIdx.x*256 + threadIdx.x) * 4;
    const float* src; __nv_bfloat16* dst;
    if (i4 < n1){ src = dec + i4; dst = g_decB + i4; }
    else if (i4 < 2*n1){ src = enc + (i4 - n1); dst = g_encB + (i4 - n1); }
    else { src = Wk + (i4 - 2*n1); dst = g_WkB + (i4 - 2*n1); }
    float4 v = *(const float4*)src;
    *(__nv_bfloat162*)dst       = __floats2bfloat162_rn(v.x, v.y);
    *(__nv_bfloat162*)(dst + 2) = __floats2bfloat162_rn(v.z, v.w);
}

// ---------------- SIMT kernels ----------------

__global__ void k_setup(const int* __restrict__ src, const float* __restrict__ Wq,
                        const float* __restrict__ bfcQ, const float* __restrict__ bq){
    const int blk = blockIdx.x, t = threadIdx.x;
    if (blk < NB){
        const int b = blk;
        __shared__ int stok[512];
        __shared__ int sfirst[512];
        __shared__ int sgarr[512];
        __shared__ unsigned sbmp[NBMPW];
        stok[t]     = src[b*TS + t];
        stok[t+256] = src[b*TS + t + 256];
        for (int i = t; i < NBMPW; i += 256) sbmp[i] = 0u;
        __syncthreads();
        for (int jj = t; jj < 512; jj += 256){
            int tok = stok[jj]; int f = 0;
            while (stok[f] != tok) f++;
            sfirst[jj] = f;
        }
        __syncthreads();
        if (t == 0){
            int run = 0;
            for (int i = 0; i < 512; i++){ sgarr[i] = run; if (sfirst[i] == i) run++; }
            g_ng[b] = run;
        }
        __syncthreads();
        for (int jj = t; jj < 512; jj += 256){
            int f = sfirst[jj], g = sgarr[f];
            g_gid[b*TS + jj] = g;
            if (f == jj){
                int tok = stok[jj];
                g_tokmap[b*VOCABSZ + tok] = g;
                atomicOr(&sbmp[tok >> 5], 1u << (tok & 31));
            }
        }
        __syncthreads();
        for (int i = t; i < NBMPW; i += 256) g_bmp[b*NBMPW + i] = sbmp[i];
    } else {
        const int row = (blk - NB)*32 + (t >> 3);
        const int l8 = t & 7;
        float s = 0.f;
        for (int k = l8; k < D; k += 8) s += Wq[(size_t)row*D + k] * bfcQ[k];
        s += __shfl_down_sync(0xFFFFFFFFu, s, 4, 8);
        s += __shfl_down_sync(0xFFFFFFFFu, s, 2, 8);
        s += __shfl_down_sync(0xFFFFFFFFu, s, 1, 8);
        if (l8 == 0) g_bc[row] = s + bq[row];
    }
}

// Wc = Wq @ WfcQ (NN), fp32 accum, bf16 output. 32x32 tiles, grid (16,16), 256 thr
__global__ void k_fold(const float* __restrict__ Wq, const float* __restrict__ WfcQ){
    __shared__ float As[32][34];
    __shared__ float Bs[32][34];
    const int t = threadIdx.x;
    const int tx = t & 15, ty = t >> 4;
    const int m0 = blockIdx.y*32, n0 = blockIdx.x*32;
    ull acc0 = 0ULL, acc1 = 0ULL;
    const int lrow = t >> 3, lc4 = t & 7;
    for (int c0 = 0; c0 < D; c0 += 32){
        float4 av = *(const float4*)(Wq   + (size_t)(m0 + lrow)*D + c0 + lc4*4);
        float4 bv = *(const float4*)(WfcQ + (size_t)(c0 + lrow)*D + n0 + lc4*4);
        __syncthreads();
        const int kb = lc4*4;
        As[kb+0][lrow]=av.x; As[kb+1][lrow]=av.y; As[kb+2][lrow]=av.z; As[kb+3][lrow]=av.w;
        Bs[lrow][kb+0]=bv.x; Bs[lrow][kb+1]=bv.y; Bs[lrow][kb+2]=bv.z; Bs[lrow][kb+3]=bv.w;
        __syncthreads();
#pragma unroll
        for (int kk = 0; kk < 32; kk++){
            float2 a = *(const float2*)&As[kk][ty*2];
            float2 b = *(const float2*)&Bs[kk][tx*2];
            ull ap = pack2f(a.x, a.y);
            ffma2(acc0, ap, pack2s(b.x));
            ffma2(acc1, ap, pack2s(b.y));
        }
    }
    float2 u0 = unpack2(acc0), u1 = unpack2(acc1);
    const int r0 = m0 + ty*2, cc = n0 + tx*2;
    *(__nv_bfloat162*)(g_WcB + (size_t)r0*D + cc)     = __floats2bfloat162_rn(u0.x, u1.x);
    *(__nv_bfloat162*)(g_WcB + (size_t)(r0+1)*D + cc) = __floats2bfloat162_rn(u0.y, u1.y);
}

// per (b,q): softmax over ts for 8 heads, head-mean, group-sum, gate w, Z
__global__ void k_attn(const float* __restrict__ dec, const float* __restrict__ Wfcw,
                       const float* __restrict__ bfcw){
    const int bq = blockIdx.x, b = bq >> 9, q = bq & 511;
    const int t = threadIdx.x, lane = t & 31, wid = t >> 5;
    __shared__ float sred[16];
    __shared__ float gsum[512];
    gsum[t] = 0.f; gsum[t+256] = 0.f;

    float acc0 = 0.f, acc1 = 0.f;
    const float* base = g_scores + ((size_t)(b*HEADS)*TQ + q) * TS;
#pragma unroll
    for (int h = 0; h < HEADS; h++){
        const float* row = base + (size_t)h * TQ * TS;
        float v0 = row[t], v1 = row[t+256];
        float m = fmaxf(v0, v1);
#pragma unroll
        for (int o = 16; o > 0; o >>= 1) m = fmaxf(m, __shfl_xor_sync(0xFFFFFFFFu, m, o));
        if (lane == 0) sred[wid] = m;
        __syncthreads();
        m = sred[0];
#pragma unroll
        for (int i = 1; i < 8; i++) m = fmaxf(m, sred[i]);
        float e0 = __expf(v0 - m), e1 = __expf(v1 - m);
        float s = e0 + e1;
#pragma unroll
        for (int o = 16; o > 0; o >>= 1) s += __shfl_xor_sync(0xFFFFFFFFu, s, o);
        if (lane == 0) sred[8 + wid] = s;
        __syncthreads();
        float ss = sred[8];
#pragma unroll
        for (int i = 9; i < 16; i++) ss += sred[i];
        float inv = 1.0f / (8.0f * ss);
        acc0 += e0 * inv; acc1 += e1 * inv;
    }

    const int* gidb = g_gid + b*TS;
    atomicAdd(&gsum[gidb[t]],     acc0);
    atomicAdd(&gsum[gidb[t+256]], acc1);

    const float* drow = dec + (size_t)bq * D;
    float pw = drow[t]*Wfcw[t] + drow[t+256]*Wfcw[t+256];
#pragma unroll
    for (int o = 16; o > 0; o >>= 1) pw += __shfl_xor_sync(0xFFFFFFFFu, pw, o);
    if (lane == 0) sred[wid] = pw;
    __syncthreads();
    float wsum = sred[0];
#pragma unroll
    for (int i = 1; i < 8; i++) wsum += sred[i];
    const float w = 1.0f / (1.0f + __expf(-(wsum + bfcw[0])));

    const int G = g_ng[b];
    float pz = 0.f;
    for (int g = t; g < G; g += 256){ float e = __expf(gsum[g]); gsum[g] = e; pz += e; }
#pragma unroll
    for (int o = 16; o > 0; o >>= 1) pz += __shfl_xor_sync(0xFFFFFFFFu, pz, o);
    if (lane == 0) sred[8 + wid] = pz;
    __syncthreads();
    float zs = sred[8];
#pragma unroll
    for (int i = 9; i < 16; i++) zs += sred[i];
    const float Z = (float)(VOCABSZ - G) + zs;
    const float wz = w / Z;

    if (t == 0){ g_wz[bq] = wz; g_cw[bq] = 1.0f - w; }
    float* gv = g_gval + (size_t)bq * TS;
    for (int g = t; g < G; g += 256) gv[g] = wz * gsum[g];
}

// final stream with inline bitmap fixups + streaming cache hints
__global__ void k_final(const float* __restrict__ p1, float* __restrict__ out){
    const int bq = blockIdx.x, b = bq >> 9;
    const int t = threadIdx.x;
    __shared__ unsigned sbmp[NBMPW];
    for (int i = t; i < NBMPW; i += 512) sbmp[i] = g_bmp[b*NBMPW + i];
    const float wz = g_wz[bq], cw = g_cw[bq];
    __syncthreads();

    const float4* p14 = (const float4*)(p1 + (size_t)bq * VOCABSZ);
    float4* o4 = (float4*)(out + (size_t)bq * VOCABSZ);
    const int* tmap = g_tokmap + (size_t)b * VOCABSZ;
    const float* gval = g_gval + (size_t)bq * TS;

#pragma unroll 4
    for (int i = t; i < VOCABSZ/4; i += 512){
        float4 v = __ldcs(&p14[i]);
        unsigned bits = (sbmp[i >> 3] >> ((i & 7) * 4)) & 0xFu;
        float4 r;
        r.x = fmaf(cw, v.x, wz); r.y = fmaf(cw, v.y, wz);
        r.z = fmaf(cw, v.z, wz); r.w = fmaf(cw, v.w, wz);
        if (bits){
            const int v0 = i * 4;
            if (bits & 1u) r.x = gval[tmap[v0+0]] + cw*v.x;
            if (bits & 2u) r.y = gval[tmap[v0+1]] + cw*v.y;
            if (bits & 4u) r.z = gval[tmap[v0+2]] + cw*v.z;
            if (bits & 8u) r.w = gval[tmap[v0+3]] + cw*v.w;
        }
        __stcs(&o4[i], r);
    }
}

// ---------------- launch ----------------
extern "C" void kernel_launch(void* const* d_in, const int* in_sizes, int n_in,
                              void* d_out, int out_size){
    int off = (in_sizes[0] == 1) ? 1 : 0;
    const float* dec  = (const float*)d_in[off + 0];
    const float* enc  = (const float*)d_in[off + 1];
    const int*   src  = (const int*)  d_in[off + 2];
    const float* p1   = (const float*)d_in[off + 3];
    const float* WfcQ = (const float*)d_in[off + 4];
    const float* bfcQ = (const float*)d_in[off + 5];
    const float* Wq   = (const float*)d_in[off + 6];
    const float* bq   = (const float*)d_in[off + 7];
    const float* Wk   = (const float*)d_in[off + 8];
    const float* bk   = (const float*)d_in[off + 9];
    const float* Wfcw = (const float*)d_in[off + 10];
    const float* bfcw = (const float*)d_in[off + 11];
    float* out = (float*)d_out;

    const int conv_blocks = (2*ROWS*D + D*D) / 4 / 256;   // 2304

    k_setup   <<<NB + 16, 256>>>(src, Wq, bfcQ, bq);
    k_tobf16  <<<conv_blocks, 256>>>(dec, enc, Wk);
    k_fold    <<<dim3(16,16), 256>>>(Wq, WfcQ);
    k_proj_h  <<<dim3(4,16,2), 256>>>(bk);
    k_scores_h<<<dim3(4,4,32), 256>>>();
    k_attn    <<<ROWS, 256>>>(dec, Wfcw, bfcw);
    k_final   <<<ROWS, 512>>>(p1, out);
}

// round 7
// speedup vs baseline: 1.7315x; 1.0412x over previous
#include <cuda_runtime.h>
#include <cuda_bf16.h>
#include <cstdint>

#define D       512
#define HEADS   8
#define DH      64
#define NB      4
#define TQ      512
#define TS      512
#define VOCABSZ 32000
#define ROWS    (NB*TQ)          // 2048
#define NBMPW   (VOCABSZ/32)     // 1000 bitmap words per batch

typedef unsigned long long ull;

// ---------------- scratch ----------------
__device__ float g_bc[D];
__device__ __nv_bfloat16 g_WcB[D*D];         // folded Wq@WfcQ (bf16)
__device__ __nv_bfloat16 g_WkB[D*D];
__device__ __nv_bfloat16 g_decB[ROWS*D];
__device__ __nv_bfloat16 g_encB[ROWS*D];
__device__ __nv_bfloat16 g_QKB[2*ROWS*D];    // Q' (=Q/8) rows [0,2048), K rows [2048,4096)
__device__ __nv_bfloat16 g_scoresB[NB*HEADS*TQ*TS];  // 16.8 MB bf16
__device__ int   g_gid[NB*TS];
__device__ int   g_ng[NB];
__device__ int   g_tokmap[NB*VOCABSZ];
__device__ unsigned g_bmp[NB*NBMPW];
__device__ float g_gval[ROWS*TS];
__device__ float g_wz[ROWS];
__device__ float g_cw[ROWS];

// ---------------- f32x2 helpers (fold kernel) ----------------
__device__ __forceinline__ ull pack2s(float x){
    ull r; asm("mov.b64 %0, {%1, %1};" : "=l"(r) : "r"(__float_as_uint(x))); return r;
}
__device__ __forceinline__ ull pack2f(float x, float y){
    ull r; asm("mov.b64 %0, {%1, %2};" : "=l"(r) : "r"(__float_as_uint(x)), "r"(__float_as_uint(y))); return r;
}
__device__ __forceinline__ void ffma2(ull& d, ull a, ull b){
    asm("fma.rn.f32x2 %0, %1, %2, %0;" : "+l"(d) : "l"(a), "l"(b));
}
__device__ __forceinline__ float2 unpack2(ull v){
    unsigned lo, hi; asm("mov.b64 {%0, %1}, %2;" : "=r"(lo), "=r"(hi) : "l"(v));
    return make_float2(__uint_as_float(lo), __uint_as_float(hi));
}

// ---------------- HMMA / cp.async helpers ----------------
__device__ __forceinline__ uint32_t smem_u32(const void* p){
    uint32_t a;
    asm("{ .reg .u64 t; cvta.to.shared.u64 t, %1; cvt.u32.u64 %0, t; }" : "=r"(a) : "l"(p));
    return a;
}
__device__ __forceinline__ void ldm_x4(uint32_t addr, uint32_t& r0, uint32_t& r1,
                                       uint32_t& r2, uint32_t& r3){
    asm volatile("ldmatrix.sync.aligned.m8n8.x4.shared.b16 {%0,%1,%2,%3}, [%4];"
        : "=r"(r0), "=r"(r1), "=r"(r2), "=r"(r3) : "r"(addr));
}
__device__ __forceinline__ void mma_bf16(float* c, uint32_t a0, uint32_t a1, uint32_t a2,
                                         uint32_t a3, uint32_t b0, uint32_t b1){
    asm volatile("mma.sync.aligned.m16n8k16.row.col.f32.bf16.bf16.f32 "
        "{%0,%1,%2,%3}, {%4,%5,%6,%7}, {%8,%9}, {%0,%1,%2,%3};"
        : "+f"(c[0]), "+f"(c[1]), "+f"(c[2]), "+f"(c[3])
        : "r"(a0), "r"(a1), "r"(a2), "r"(a3), "r"(b0), "r"(b1));
}
__device__ __forceinline__ void cp16(uint32_t dst, const void* src){
    asm volatile("cp.async.cg.shared.global [%0], [%1], 16;" :: "r"(dst), "l"(src));
}
#define CP_COMMIT() asm volatile("cp.async.commit_group;" ::: "memory")
#define CP_WAIT(n)  asm volatile("cp.async.wait_group %0;" :: "n"(n) : "memory")

// ---- 128x128-tile NT GEMM on HMMA, cp.async double-buffered. ----
// A,B bf16 row-major [*,512]. C = (A.B^T [+bias]) * alpha. K = NCHUNK*64.
// 256 threads = 8 warps (2 m x 4 n), warp tile 64x32.
template<int NCHUNK, bool OUT_BF16, bool BIAS>
__device__ __forceinline__ void hgemm_nt(
    const __nv_bfloat16* __restrict__ A, const __nv_bfloat16* __restrict__ B,
    void* __restrict__ Cout, int ldc, const float* __restrict__ bias,
    float alpha, int m0, int n0)
{
    // buffer b: A at b*32768, B at b*32768 + 16384 ; each 128 rows x 128B, swizzled
    __shared__ __align__(16) uint8_t sm[2*32768];
    const int tid = threadIdx.x;
    const int w = tid >> 5, lane = tid & 31;
    const int wm = w >> 2, wn = w & 3;
    const uint32_t sbase = smem_u32(sm);

    float acc[4][4][4];
#pragma unroll
    for (int i=0;i<4;i++)
#pragma unroll
        for (int j=0;j<4;j++)
#pragma unroll
            for (int k=0;k<4;k++) acc[i][j][k] = 0.f;

    // per-thread load coords: 8 x 16B per buffer half (A and B each: 4 iters)
    const int lr = tid >> 1;                 // handled pair base: rows tid>>1 ... pattern below
    (void)lr;

    // issue loads of chunk c into buffer bsel
    auto issue = [&](int c, int bsel){
        const uint32_t dstA = sbase + bsel*32768;
        const uint32_t dstB = dstA + 16384;
#pragma unroll
        for (int it = 0; it < 4; it++){
            const int i = tid + it*256;      // 0..1023
            const int r = i >> 3, cb = i & 7;
            const int sw = (cb ^ (r & 7)) << 4;
            cp16(dstA + r*128 + sw, A + (size_t)(m0 + r)*512 + c*64 + cb*8);
            cp16(dstB + r*128 + sw, B + (size_t)(n0 + r)*512 + c*64 + cb*8);
        }
        CP_COMMIT();
    };

    issue(0, 0);
    if (NCHUNK > 1) issue(1, 1);

    // per-lane ldmatrix address components
    const int rowA_l = (lane & 7) + ((lane >> 3) & 1) * 8;  // + wm*64 + fm*16
    const int kbA_l  = lane >> 4;                           // 0/1
    const int rowB_l = (lane & 7) + ((lane >> 4) & 1) * 8;  // + wn*32 + fn*16
    const int kbB_l  = (lane >> 3) & 1;

#pragma unroll
    for (int c = 0; c < NCHUNK; c++){
        if (c + 1 < NCHUNK) { CP_WAIT(1); } else { CP_WAIT(0); }
        __syncthreads();
        const uint32_t sA = sbase + (c & 1)*32768;
        const uint32_t sB = sA + 16384;
#pragma unroll
        for (int ks = 0; ks < 4; ks++){
            uint32_t af[4][4];
#pragma unroll
            for (int fm = 0; fm < 4; fm++){
                const int row = wm*64 + fm*16 + rowA_l;
                const int kb  = ks*2 + kbA_l;
                ldm_x4(sA + row*128 + ((kb ^ (row & 7)) << 4),
                       af[fm][0], af[fm][1], af[fm][2], af[fm][3]);
            }
            uint32_t bf[2][4];
#pragma unroll
            for (int fn = 0; fn < 2; fn++){
                const int row = wn*32 + fn*16 + rowB_l;
                const int kb  = ks*2 + kbB_l;
                ldm_x4(sB + row*128 + ((kb ^ (row & 7)) << 4),
                       bf[fn][0], bf[fn][1], bf[fn][2], bf[fn][3]);
            }
#pragma unroll
            for (int fm = 0; fm < 4; fm++)
#pragma unroll
                for (int j = 0; j < 4; j++)
                    mma_bf16(acc[fm][j], af[fm][0], af[fm][1], af[fm][2], af[fm][3],
                             bf[j>>1][(j&1)*2], bf[j>>1][(j&1)*2 + 1]);
        }
        __syncthreads();                      // everyone done reading buf (c&1)
        if (c + 2 < NCHUNK) issue(c + 2, c & 1);
    }

    // epilogue
    const int r_l = lane >> 2, c_l = (lane & 3) * 2;
#pragma unroll
    for (int fm = 0; fm < 4; fm++){
#pragma unroll
        for (int j = 0; j < 4; j++){
            const int row = m0 + wm*64 + fm*16 + r_l;
            const int col = n0 + wn*32 + (j>>1)*16 + (j&1)*8 + c_l;
            const float* a = acc[fm][j];
            float b0 = 0.f, b1 = 0.f;
            if (BIAS){ b0 = bias[col]; b1 = bias[col+1]; }
            if (OUT_BF16){
                __nv_bfloat16* O = (__nv_bfloat16*)Cout;
                *(__nv_bfloat162*)(O + (size_t)row*ldc + col) =
                    __floats2bfloat162_rn((a[0]+b0)*alpha, (a[1]+b1)*alpha);
                *(__nv_bfloat162*)(O + (size_t)(row+8)*ldc + col) =
                    __floats2bfloat162_rn((a[2]+b0)*alpha, (a[3]+b1)*alpha);
            } else {
                float* O = (float*)Cout;
                *(float2*)(O + (size_t)row*ldc + col) = make_float2((a[0]+b0)*alpha, (a[1]+b1)*alpha);
                *(float2*)(O + (size_t)(row+8)*ldc + col) = make_float2((a[2]+b0)*alpha, (a[3]+b1)*alpha);
            }
        }
    }
}

// z=0: Q' = (dec@Wc^T + bc)/8 ; z=1: K = enc@Wk^T + bk.  grid (4,16,2) x 256 thr
__global__ void __launch_bounds__(256) k_proj_h(const float* __restrict__ bk){
    if (blockIdx.z == 0)
        hgemm_nt<8,true,true>(g_decB, g_WcB, g_QKB, 512, g_bc, 0.125f,
                              blockIdx.y*128, blockIdx.x*128);
    else
        hgemm_nt<8,true,true>(g_encB, g_WkB, g_QKB + (size_t)ROWS*D, 512, bk, 1.0f,
                              blockIdx.y*128, blockIdx.x*128);
}

// scores[b,h] = Q'h @ Kh^T  (bf16 out).  grid (4,4,32) x 256 thr
__global__ void __launch_bounds__(256) k_scores_h(){
    const int z = blockIdx.z, b = z >> 3, h = z & 7;
    hgemm_nt<1,true,false>(g_QKB + (size_t)(b*TQ)*D + h*DH,
                           g_QKB + (size_t)(ROWS + b*TS)*D + h*DH,
                           g_scoresB + (size_t)z*TQ*TS, TS, nullptr, 1.0f,
                           blockIdx.y*128, blockIdx.x*128);
}

// ---------------- fp32 -> bf16 conversion (dec, enc, Wk) ----------------
__global__ void k_tobf16(const float* __restrict__ dec, const float* __restrict__ enc,
                         const float* __restrict__ Wk){
    const int n1 = ROWS*D;
    const int i4 = (blockIdx.x*256 + threadIdx.x) * 4;
    const float* src; __nv_bfloat16* dst;
    if (i4 < n1){ src = dec + i4; dst = g_decB + i4; }
    else if (i4 < 2*n1){ src = enc + (i4 - n1); dst = g_encB + (i4 - n1); }
    else { src = Wk + (i4 - 2*n1); dst = g_WkB + (i4 - 2*n1); }
    float4 v = *(const float4*)src;
    *(__nv_bfloat162*)dst       = __floats2bfloat162_rn(v.x, v.y);
    *(__nv_bfloat162*)(dst + 2) = __floats2bfloat162_rn(v.z, v.w);
}

// ---------------- SIMT kernels ----------------

__global__ void k_setup(const int* __restrict__ src, const float* __restrict__ Wq,
                        const float* __restrict__ bfcQ, const float* __restrict__ bq){
    const int blk = blockIdx.x, t = threadIdx.x;
    if (blk < NB){
        const int b = blk;
        __shared__ int stok[512];
        __shared__ int sfirst[512];
        __shared__ int sgarr[512];
        __shared__ unsigned sbmp[NBMPW];
        stok[t]     = src[b*TS + t];
        stok[t+256] = src[b*TS + t + 256];
        for (int i = t; i < NBMPW; i += 256) sbmp[i] = 0u;
        __syncthreads();
        for (int jj = t; jj < 512; jj += 256){
            int tok = stok[jj]; int f = 0;
            while (stok[f] != tok) f++;
            sfirst[jj] = f;
        }
        __syncthreads();
        if (t == 0){
            int run = 0;
            for (int i = 0; i < 512; i++){ sgarr[i] = run; if (sfirst[i] == i) run++; }
            g_ng[b] = run;
        }
        __syncthreads();
        for (int jj = t; jj < 512; jj += 256){
            int f = sfirst[jj], g = sgarr[f];
            g_gid[b*TS + jj] = g;
            if (f == jj){
                int tok = stok[jj];
                g_tokmap[b*VOCABSZ + tok] = g;
                atomicOr(&sbmp[tok >> 5], 1u << (tok & 31));
            }
        }
        __syncthreads();
        for (int i = t; i < NBMPW; i += 256) g_bmp[b*NBMPW + i] = sbmp[i];
    } else {
        const int row = (blk - NB)*32 + (t >> 3);
        const int l8 = t & 7;
        float s = 0.f;
        for (int k = l8; k < D; k += 8) s += Wq[(size_t)row*D + k] * bfcQ[k];
        s += __shfl_down_sync(0xFFFFFFFFu, s, 4, 8);
        s += __shfl_down_sync(0xFFFFFFFFu, s, 2, 8);
        s += __shfl_down_sync(0xFFFFFFFFu, s, 1, 8);
        if (l8 == 0) g_bc[row] = s + bq[row];
    }
}

// Wc = Wq @ WfcQ (NN), fp32 accum, bf16 output. 32x32 tiles, grid (16,16), 256 thr
__global__ void k_fold(const float* __restrict__ Wq, const float* __restrict__ WfcQ){
    __shared__ float As[32][34];
    __shared__ float Bs[32][34];
    const int t = threadIdx.x;
    const int tx = t & 15, ty = t >> 4;
    const int m0 = blockIdx.y*32, n0 = blockIdx.x*32;
    ull acc0 = 0ULL, acc1 = 0ULL;
    const int lrow = t >> 3, lc4 = t & 7;
    for (int c0 = 0; c0 < D; c0 += 32){
        float4 av = *(const float4*)(Wq   + (size_t)(m0 + lrow)*D + c0 + lc4*4);
        float4 bv = *(const float4*)(WfcQ + (size_t)(c0 + lrow)*D + n0 + lc4*4);
        __syncthreads();
        const int kb = lc4*4;
        As[kb+0][lrow]=av.x; As[kb+1][lrow]=av.y; As[kb+2][lrow]=av.z; As[kb+3][lrow]=av.w;
        Bs[lrow][kb+0]=bv.x; Bs[lrow][kb+1]=bv.y; Bs[lrow][kb+2]=bv.z; Bs[lrow][kb+3]=bv.w;
        __syncthreads();
#pragma unroll
        for (int kk = 0; kk < 32; kk++){
            float2 a = *(const float2*)&As[kk][ty*2];
            float2 b = *(const float2*)&Bs[kk][tx*2];
            ull ap = pack2f(a.x, a.y);
            ffma2(acc0, ap, pack2s(b.x));
            ffma2(acc1, ap, pack2s(b.y));
        }
    }
    float2 u0 = unpack2(acc0), u1 = unpack2(acc1);
    const int r0 = m0 + ty*2, cc = n0 + tx*2;
    *(__nv_bfloat162*)(g_WcB + (size_t)r0*D + cc)     = __floats2bfloat162_rn(u0.x, u1.x);
    *(__nv_bfloat162*)(g_WcB + (size_t)(r0+1)*D + cc) = __floats2bfloat162_rn(u0.y, u1.y);
}

// per (b,q): softmax over ts for 8 heads (bf16 scores), head-mean, group-sum, gate, Z
__global__ void k_attn(const float* __restrict__ dec, const float* __restrict__ Wfcw,
                       const float* __restrict__ bfcw){
    const int bq = blockIdx.x, b = bq >> 9, q = bq & 511;
    const int t = threadIdx.x, lane = t & 31, wid = t >> 5;
    __shared__ float sred[16];
    __shared__ float gsum[512];
    gsum[t] = 0.f; gsum[t+256] = 0.f;

    float acc0 = 0.f, acc1 = 0.f;   // elements 2t, 2t+1
    const __nv_bfloat16* base = g_scoresB + ((size_t)(b*HEADS)*TQ + q) * TS;
#pragma unroll
    for (int h = 0; h < HEADS; h++){
        const __nv_bfloat16* row = base + (size_t)h * TQ * TS;
        const __nv_bfloat162 vv = *(const __nv_bfloat162*)(row + 2*t);
        float v0 = __bfloat162float(vv.x), v1 = __bfloat162float(vv.y);
        float m = fmaxf(v0, v1);
#pragma unroll
        for (int o = 16; o > 0; o >>= 1) m = fmaxf(m, __shfl_xor_sync(0xFFFFFFFFu, m, o));
        if (lane == 0) sred[wid] = m;
        __syncthreads();
        m = sred[0];
#pragma unroll
        for (int i = 1; i < 8; i++) m = fmaxf(m, sred[i]);
        float e0 = __expf(v0 - m), e1 = __expf(v1 - m);
        float s = e0 + e1;
#pragma unroll
        for (int o = 16; o > 0; o >>= 1) s += __shfl_xor_sync(0xFFFFFFFFu, s, o);
        if (lane == 0) sred[8 + wid] = s;
        __syncthreads();
        float ss = sred[8];
#pragma unroll
        for (int i = 9; i < 16; i++) ss += sred[i];
        float inv = 1.0f / (8.0f * ss);
        acc0 += e0 * inv; acc1 += e1 * inv;
    }

    const int* gidb = g_gid + b*TS;
    atomicAdd(&gsum[gidb[2*t]],     acc0);
    atomicAdd(&gsum[gidb[2*t + 1]], acc1);

    const float* drow = dec + (size_t)bq * D;
    float pw = drow[t]*Wfcw[t] + drow[t+256]*Wfcw[t+256];
#pragma unroll
    for (int o = 16; o > 0; o >>= 1) pw += __shfl_xor_sync(0xFFFFFFFFu, pw, o);
    if (lane == 0) sred[wid] = pw;
    __syncthreads();                      // also fences the smem atomics
    float wsum = sred[0];
#pragma unroll
    for (int i = 1; i < 8; i++) wsum += sred[i];
    const float w = 1.0f / (1.0f + __expf(-(wsum + bfcw[0])));

    const int G = g_ng[b];
    float pz = 0.f;
    for (int g = t; g < G; g += 256){ float e = __expf(gsum[g]); gsum[g] = e; pz += e; }
#pragma unroll
    for (int o = 16; o > 0; o >>= 1) pz += __shfl_xor_sync(0xFFFFFFFFu, pz, o);
    if (lane == 0) sred[8 + wid] = pz;
    __syncthreads();
    float zs = sred[8];
#pragma unroll
    for (int i = 9; i < 16; i++) zs += sred[i];
    const float Z = (float)(VOCABSZ - G) + zs;
    const float wz = w / Z;

    if (t == 0){ g_wz[bq] = wz; g_cw[bq] = 1.0f - w; }
    float* gv = g_gval + (size_t)bq * TS;
    for (int g = t; g < G; g += 256) gv[g] = wz * gsum[g];
}

// final stream with inline bitmap fixups + streaming cache hints
__global__ void k_final(const float* __restrict__ p1, float* __restrict__ out){
    const int bq = blockIdx.x, b = bq >> 9;
    const int t = threadIdx.x;
    __shared__ unsigned sbmp[NBMPW];
    for (int i = t; i < NBMPW; i += 512) sbmp[i] = g_bmp[b*NBMPW + i];
    const float wz = g_wz[bq], cw = g_cw[bq];
    __syncthreads();

    const float4* p14 = (const float4*)(p1 + (size_t)bq * VOCABSZ);
    float4* o4 = (float4*)(out + (size_t)bq * VOCABSZ);
    const int* tmap = g_tokmap + (size_t)b * VOCABSZ;
    const float* gval = g_gval + (size_t)bq * TS;

#pragma unroll 4
    for (int i = t; i < VOCABSZ/4; i += 512){
        float4 v = __ldcs(&p14[i]);
        unsigned bits = (sbmp[i >> 3] >> ((i & 7) * 4)) & 0xFu;
        float4 r;
        r.x = fmaf(cw, v.x, wz); r.y = fmaf(cw, v.y, wz);
        r.z = fmaf(cw, v.z, wz); r.w = fmaf(cw, v.w, wz);
        if (bits){
            const int v0 = i * 4;
            if (bits & 1u) r.x = gval[tmap[v0+0]] + cw*v.x;
            if (bits & 2u) r.y = gval[tmap[v0+1]] + cw*v.y;
            if (bits & 4u) r.z = gval[tmap[v0+2]] + cw*v.z;
            if (bits & 8u) r.w = gval[tmap[v0+3]] + cw*v.w;
        }
        __stcs(&o4[i], r);
    }
}

// ---------------- launch ----------------
extern "C" void kernel_launch(void* const* d_in, const int* in_sizes, int n_in,
                              void* d_out, int out_size){
    int off = (in_sizes[0] == 1) ? 1 : 0;
    const float* dec  = (const float*)d_in[off + 0];
    const float* enc  = (const float*)d_in[off + 1];
    const int*   src  = (const int*)  d_in[off + 2];
    const float* p1   = (const float*)d_in[off + 3];
    const float* WfcQ = (const float*)d_in[off + 4];
    const float* bfcQ = (const float*)d_in[off + 5];
    const float* Wq   = (const float*)d_in[off + 6];
    const float* bq   = (const float*)d_in[off + 7];
    const float* Wk   = (const float*)d_in[off + 8];
    const float* bk   = (const float*)d_in[off + 9];
    const float* Wfcw = (const float*)d_in[off + 10];
    const float* bfcw = (const float*)d_in[off + 11];
    float* out = (float*)d_out;

    const int conv_blocks = (2*ROWS*D + D*D) / 4 / 256;   // 2304

    k_setup   <<<NB + 16, 256>>>(src, Wq, bfcQ, bq);
    k_tobf16  <<<conv_blocks, 256>>>(dec, enc, Wk);
    k_fold    <<<dim3(16,16), 256>>>(Wq, WfcQ);
    k_proj_h  <<<dim3(4,16,2), 256>>>(bk);
    k_scores_h<<<dim3(4,4,32), 256>>>();
    k_attn    <<<ROWS, 256>>>(dec, Wfcw, bfcw);
    k_final   <<<ROWS, 512>>>(p1, out);
}

// round 8
// speedup vs baseline: 1.9708x; 1.1382x over previous
#include <cuda_runtime.h>
#include <cuda_bf16.h>
#include <cstdint>

#define D       512
#define HEADS   8
#define DH      64
#define NB      4
#define TQ      512
#define TS      512
#define VOCABSZ 32000
#define ROWS    (NB*TQ)          // 2048
#define NBMPW   (VOCABSZ/32)     // 1000 bitmap words per batch

typedef unsigned long long ull;

// ---------------- scratch ----------------
__device__ float g_bc[D];
__device__ __nv_bfloat16 g_WcB[D*D];         // folded Wq@WfcQ (bf16)
__device__ __nv_bfloat16 g_WkB[D*D];
__device__ __nv_bfloat16 g_decB[ROWS*D];
__device__ __nv_bfloat16 g_encB[ROWS*D];
__device__ __nv_bfloat16 g_QKB[2*ROWS*D];    // Q' (=Q/8) rows [0,2048), K rows [2048,4096)
__device__ __nv_bfloat16 g_scoresB[NB*HEADS*TQ*TS];  // 16.8 MB bf16
__device__ int   g_gid[NB*TS];
__device__ int   g_ng[NB];
__device__ int   g_tokmap[NB*VOCABSZ];
__device__ unsigned g_bmp[NB*NBMPW];
__device__ float g_gval[ROWS*TS];
__device__ float g_wz[ROWS];
__device__ float g_cw[ROWS];

// ---------------- f32x2 helpers (fold) ----------------
__device__ __forceinline__ ull pack2s(float x){
    ull r; asm("mov.b64 %0, {%1, %1};" : "=l"(r) : "r"(__float_as_uint(x))); return r;
}
__device__ __forceinline__ ull pack2f(float x, float y){
    ull r; asm("mov.b64 %0, {%1, %2};" : "=l"(r) : "r"(__float_as_uint(x)), "r"(__float_as_uint(y))); return r;
}
__device__ __forceinline__ void ffma2(ull& d, ull a, ull b){
    asm("fma.rn.f32x2 %0, %1, %2, %0;" : "+l"(d) : "l"(a), "l"(b));
}
__device__ __forceinline__ float2 unpack2(ull v){
    unsigned lo, hi; asm("mov.b64 {%0, %1}, %2;" : "=r"(lo), "=r"(hi) : "l"(v));
    return make_float2(__uint_as_float(lo), __uint_as_float(hi));
}

// ---------------- HMMA / cp.async helpers ----------------
__device__ __forceinline__ uint32_t smem_u32(const void* p){
    uint32_t a;
    asm("{ .reg .u64 t; cvta.to.shared.u64 t, %1; cvt.u32.u64 %0, t; }" : "=r"(a) : "l"(p));
    return a;
}
__device__ __forceinline__ void ldm_x4(uint32_t addr, uint32_t& r0, uint32_t& r1,
                                       uint32_t& r2, uint32_t& r3){
    asm volatile("ldmatrix.sync.aligned.m8n8.x4.shared.b16 {%0,%1,%2,%3}, [%4];"
        : "=r"(r0), "=r"(r1), "=r"(r2), "=r"(r3) : "r"(addr));
}
__device__ __forceinline__ void mma_bf16(float* c, uint32_t a0, uint32_t a1, uint32_t a2,
                                         uint32_t a3, uint32_t b0, uint32_t b1){
    asm volatile("mma.sync.aligned.m16n8k16.row.col.f32.bf16.bf16.f32 "
        "{%0,%1,%2,%3}, {%4,%5,%6,%7}, {%8,%9}, {%0,%1,%2,%3};"
        : "+f"(c[0]), "+f"(c[1]), "+f"(c[2]), "+f"(c[3])
        : "r"(a0), "r"(a1), "r"(a2), "r"(a3), "r"(b0), "r"(b1));
}
__device__ __forceinline__ void cp16(uint32_t dst, const void* src){
    asm volatile("cp.async.cg.shared.global [%0], [%1], 16;" :: "r"(dst), "l"(src));
}
#define CP_COMMIT() asm volatile("cp.async.commit_group;" ::: "memory")
#define CP_WAIT(n)  asm volatile("cp.async.wait_group %0;" :: "n"(n) : "memory")

// ---- 128x128-tile NT GEMM on HMMA, cp.async double-buffered ----
template<int NCHUNK, bool OUT_BF16, bool BIAS>
__device__ __forceinline__ void hgemm_nt(
    const __nv_bfloat16* __restrict__ A, const __nv_bfloat16* __restrict__ B,
    void* __restrict__ Cout, int ldc, const float* __restrict__ bias,
    float alpha, int m0, int n0)
{
    __shared__ __align__(16) uint8_t sm[2*32768];
    const int tid = threadIdx.x;
    const int w = tid >> 5, lane = tid & 31;
    const int wm = w >> 2, wn = w & 3;
    const uint32_t sbase = smem_u32(sm);

    float acc[4][4][4];
#pragma unroll
    for (int i=0;i<4;i++)
#pragma unroll
        for (int j=0;j<4;j++)
#pragma unroll
            for (int k=0;k<4;k++) acc[i][j][k] = 0.f;

    auto issue = [&](int c, int bsel){
        const uint32_t dstA = sbase + bsel*32768;
        const uint32_t dstB = dstA + 16384;
#pragma unroll
        for (int it = 0; it < 4; it++){
            const int i = tid + it*256;
            const int r = i >> 3, cb = i & 7;
            const int sw = (cb ^ (r & 7)) << 4;
            cp16(dstA + r*128 + sw, A + (size_t)(m0 + r)*512 + c*64 + cb*8);
            cp16(dstB + r*128 + sw, B + (size_t)(n0 + r)*512 + c*64 + cb*8);
        }
        CP_COMMIT();
    };

    issue(0, 0);
    if (NCHUNK > 1) issue(1, 1);

    const int rowA_l = (lane & 7) + ((lane >> 3) & 1) * 8;
    const int kbA_l  = lane >> 4;
    const int rowB_l = (lane & 7) + ((lane >> 4) & 1) * 8;
    const int kbB_l  = (lane >> 3) & 1;

#pragma unroll
    for (int c = 0; c < NCHUNK; c++){
        if (c + 1 < NCHUNK) { CP_WAIT(1); } else { CP_WAIT(0); }
        __syncthreads();
        const uint32_t sA = sbase + (c & 1)*32768;
        const uint32_t sB = sA + 16384;
#pragma unroll
        for (int ks = 0; ks < 4; ks++){
            uint32_t af[4][4];
#pragma unroll
            for (int fm = 0; fm < 4; fm++){
                const int row = wm*64 + fm*16 + rowA_l;
                const int kb  = ks*2 + kbA_l;
                ldm_x4(sA + row*128 + ((kb ^ (row & 7)) << 4),
                       af[fm][0], af[fm][1], af[fm][2], af[fm][3]);
            }
            uint32_t bf[2][4];
#pragma unroll
            for (int fn = 0; fn < 2; fn++){
                const int row = wn*32 + fn*16 + rowB_l;
                const int kb  = ks*2 + kbB_l;
                ldm_x4(sB + row*128 + ((kb ^ (row & 7)) << 4),
                       bf[fn][0], bf[fn][1], bf[fn][2], bf[fn][3]);
            }
#pragma unroll
            for (int fm = 0; fm < 4; fm++)
#pragma unroll
                for (int j = 0; j < 4; j++)
                    mma_bf16(acc[fm][j], af[fm][0], af[fm][1], af[fm][2], af[fm][3],
                             bf[j>>1][(j&1)*2], bf[j>>1][(j&1)*2 + 1]);
        }
        __syncthreads();
        if (c + 2 < NCHUNK) issue(c + 2, c & 1);
    }

    const int r_l = lane >> 2, c_l = (lane & 3) * 2;
#pragma unroll
    for (int fm = 0; fm < 4; fm++){
#pragma unroll
        for (int j = 0; j < 4; j++){
            const int row = m0 + wm*64 + fm*16 + r_l;
            const int col = n0 + wn*32 + (j>>1)*16 + (j&1)*8 + c_l;
            const float* a = acc[fm][j];
            float b0 = 0.f, b1 = 0.f;
            if (BIAS){ b0 = bias[col]; b1 = bias[col+1]; }
            if (OUT_BF16){
                __nv_bfloat16* O = (__nv_bfloat16*)Cout;
                *(__nv_bfloat162*)(O + (size_t)row*ldc + col) =
                    __floats2bfloat162_rn((a[0]+b0)*alpha, (a[1]+b1)*alpha);
                *(__nv_bfloat162*)(O + (size_t)(row+8)*ldc + col) =
                    __floats2bfloat162_rn((a[2]+b0)*alpha, (a[3]+b1)*alpha);
            } else {
                float* O = (float*)Cout;
                *(float2*)(O + (size_t)row*ldc + col) = make_float2((a[0]+b0)*alpha, (a[1]+b1)*alpha);
                *(float2*)(O + (size_t)(row+8)*ldc + col) = make_float2((a[2]+b0)*alpha, (a[3]+b1)*alpha);
            }
        }
    }
}

__global__ void __launch_bounds__(256) k_proj_h(const float* __restrict__ bk){
    if (blockIdx.z == 0)
        hgemm_nt<8,true,true>(g_decB, g_WcB, g_QKB, 512, g_bc, 0.125f,
                              blockIdx.y*128, blockIdx.x*128);
    else
        hgemm_nt<8,true,true>(g_encB, g_WkB, g_QKB + (size_t)ROWS*D, 512, bk, 1.0f,
                              blockIdx.y*128, blockIdx.x*128);
}

__global__ void __launch_bounds__(256) k_scores_h(){
    const int z = blockIdx.z, b = z >> 3, h = z & 7;
    hgemm_nt<1,true,false>(g_QKB + (size_t)(b*TQ)*D + h*DH,
                           g_QKB + (size_t)(ROWS + b*TS)*D + h*DH,
                           g_scoresB + (size_t)z*TQ*TS, TS, nullptr, 1.0f,
                           blockIdx.y*128, blockIdx.x*128);
}

// ---------------- merged prep kernel: convert | grouping | bc | fold ----------------
// blocks [0,2304): fp32->bf16 ; [2304,2308): grouping ; [2308,2324): bc ; [2324,2580): fold
#define PREP_CONV   2304
#define PREP_GRP    (PREP_CONV + NB)       // 2308
#define PREP_BC     (PREP_GRP + 16)        // 2324
#define PREP_TOTAL  (PREP_BC + 256)        // 2580

__global__ void k_prep(const int* __restrict__ src,
                       const float* __restrict__ Wq, const float* __restrict__ bfcQ,
                       const float* __restrict__ bq, const float* __restrict__ WfcQ,
                       const float* __restrict__ dec, const float* __restrict__ enc,
                       const float* __restrict__ Wk){
    __shared__ __align__(16) uint8_t shraw[10496];
    const int blk = blockIdx.x, t = threadIdx.x;

    if (blk < PREP_CONV){
        const int n1 = ROWS*D;
        const int i4 = (blk*256 + t) * 4;
        const float* s; __nv_bfloat16* d;
        if (i4 < n1){ s = dec + i4; d = g_decB + i4; }
        else if (i4 < 2*n1){ s = enc + (i4 - n1); d = g_encB + (i4 - n1); }
        else { s = Wk + (i4 - 2*n1); d = g_WkB + (i4 - 2*n1); }
        float4 v = *(const float4*)s;
        *(__nv_bfloat162*)d       = __floats2bfloat162_rn(v.x, v.y);
        *(__nv_bfloat162*)(d + 2) = __floats2bfloat162_rn(v.z, v.w);
    } else if (blk < PREP_GRP){
        const int b = blk - PREP_CONV;
        int* stok   = (int*)shraw;                 // 512
        int* sfirst = stok + 512;                  // 512
        int* sgarr  = sfirst + 512;                // 512
        unsigned* sbmp = (unsigned*)(sgarr + 512); // 1000
        stok[t]     = src[b*TS + t];
        stok[t+256] = src[b*TS + t + 256];
        for (int i = t; i < NBMPW; i += 256) sbmp[i] = 0u;
        __syncthreads();
        for (int jj = t; jj < 512; jj += 256){
            int tok = stok[jj]; int f = 0;
            while (stok[f] != tok) f++;
            sfirst[jj] = f;
        }
        __syncthreads();
        if (t == 0){
            int run = 0;
            for (int i = 0; i < 512; i++){ sgarr[i] = run; if (sfirst[i] == i) run++; }
            g_ng[b] = run;
        }
        __syncthreads();
        for (int jj = t; jj < 512; jj += 256){
            int f = sfirst[jj], g = sgarr[f];
            g_gid[b*TS + jj] = g;
            if (f == jj){
                int tok = stok[jj];
                g_tokmap[b*VOCABSZ + tok] = g;
                atomicOr(&sbmp[tok >> 5], 1u << (tok & 31));
            }
        }
        __syncthreads();
        for (int i = t; i < NBMPW; i += 256) g_bmp[b*NBMPW + i] = sbmp[i];
    } else if (blk < PREP_BC){
        const int row = (blk - PREP_GRP)*32 + (t >> 3);
        const int l8 = t & 7;
        float s = 0.f;
        for (int k = l8; k < D; k += 8) s += Wq[(size_t)row*D + k] * bfcQ[k];
        s += __shfl_down_sync(0xFFFFFFFFu, s, 4, 8);
        s += __shfl_down_sync(0xFFFFFFFFu, s, 2, 8);
        s += __shfl_down_sync(0xFFFFFFFFu, s, 1, 8);
        if (l8 == 0) g_bc[row] = s + bq[row];
    } else {
        // fold: Wc = Wq @ WfcQ (NN), bf16 out. 32x32 tiles.
        const int idx = blk - PREP_BC;
        const int m0 = (idx >> 4)*32, n0 = (idx & 15)*32;
        float (*As)[34] = (float(*)[34])shraw;
        float (*Bs)[34] = (float(*)[34])(shraw + 4352);
        const int tx = t & 15, ty = t >> 4;
        ull acc0 = 0ULL, acc1 = 0ULL;
        const int lrow = t >> 3, lc4 = t & 7;
        for (int c0 = 0; c0 < D; c0 += 32){
            float4 av = *(const float4*)(Wq   + (size_t)(m0 + lrow)*D + c0 + lc4*4);
            float4 bv = *(const float4*)(WfcQ + (size_t)(c0 + lrow)*D + n0 + lc4*4);
            __syncthreads();
            const int kb = lc4*4;
            As[kb+0][lrow]=av.x; As[kb+1][lrow]=av.y; As[kb+2][lrow]=av.z; As[kb+3][lrow]=av.w;
            Bs[lrow][kb+0]=bv.x; Bs[lrow][kb+1]=bv.y; Bs[lrow][kb+2]=bv.z; Bs[lrow][kb+3]=bv.w;
            __syncthreads();
#pragma unroll
            for (int kk = 0; kk < 32; kk++){
                float2 a = *(const float2*)&As[kk][ty*2];
                float2 b = *(const float2*)&Bs[kk][tx*2];
                ull ap = pack2f(a.x, a.y);
                ffma2(acc0, ap, pack2s(b.x));
                ffma2(acc1, ap, pack2s(b.y));
            }
        }
        float2 u0 = unpack2(acc0), u1 = unpack2(acc1);
        const int r0 = m0 + ty*2, cc = n0 + tx*2;
        *(__nv_bfloat162*)(g_WcB + (size_t)r0*D + cc)     = __floats2bfloat162_rn(u0.x, u1.x);
        *(__nv_bfloat162*)(g_WcB + (size_t)(r0+1)*D + cc) = __floats2bfloat162_rn(u0.y, u1.y);
    }
}

// ---------------- warp-per-head attention combine ----------------
// block = (b,q), 256 threads = 8 warps = 8 heads. 4 block barriers total.
__global__ void __launch_bounds__(256) k_attn(
    const float* __restrict__ dec, const float* __restrict__ Wfcw,
    const float* __restrict__ bfcw){
    const int bq = blockIdx.x, b = bq >> 9, q = bq & 511;
    const int t = threadIdx.x, lane = t & 31, h = t >> 5;
    __shared__ float sattn[HEADS][512];
    __shared__ float gsum[512];
    __shared__ float sinv[HEADS];
    __shared__ float sred[16];
    gsum[t] = 0.f; gsum[t+256] = 0.f;

    // warp h: full softmax numerators for head h (coalesced uint2 loads, shuffle reductions)
    const uint2* rp = (const uint2*)(g_scoresB + ((size_t)(b*HEADS + h)*TQ + q) * TS);
    float4 ev[4];
    float m = -1e30f;
#pragma unroll
    for (int j = 0; j < 4; j++){
        const uint2 u = rp[lane + 32*j];
        const __nv_bfloat162 p0 = *(const __nv_bfloat162*)&u.x;
        const __nv_bfloat162 p1 = *(const __nv_bfloat162*)&u.y;
        float4 v = make_float4(__bfloat162float(p0.x), __bfloat162float(p0.y),
                               __bfloat162float(p1.x), __bfloat162float(p1.y));
        ev[j] = v;
        m = fmaxf(m, fmaxf(fmaxf(v.x, v.y), fmaxf(v.z, v.w)));
    }
#pragma unroll
    for (int o = 16; o > 0; o >>= 1) m = fmaxf(m, __shfl_xor_sync(0xFFFFFFFFu, m, o));
    float s = 0.f;
#pragma unroll
    for (int j = 0; j < 4; j++){
        ev[j].x = __expf(ev[j].x - m); ev[j].y = __expf(ev[j].y - m);
        ev[j].z = __expf(ev[j].z - m); ev[j].w = __expf(ev[j].w - m);
        s += ev[j].x + ev[j].y + ev[j].z + ev[j].w;
    }
#pragma unroll
    for (int o = 16; o > 0; o >>= 1) s += __shfl_xor_sync(0xFFFFFFFFu, s, o);
    if (lane == 0) sinv[h] = 1.0f / (8.0f * s);
#pragma unroll
    for (int j = 0; j < 4; j++)
        *(float4*)&sattn[h][(lane + 32*j)*4] = ev[j];   // conflict-free STS.128
    __syncthreads();

    // gather heads + scatter into token groups
    const int* gidb = g_gid + b*TS;
    float iv[HEADS];
#pragma unroll
    for (int hh = 0; hh < HEADS; hh++) iv[hh] = sinv[hh];
#pragma unroll
    for (int half = 0; half < 2; half++){
        const int ts = t + half*256;
        float a = 0.f;
#pragma unroll
        for (int hh = 0; hh < HEADS; hh++) a += sattn[hh][ts] * iv[hh];
        atomicAdd(&gsum[gidb[ts]], a);
    }

    // gate w = sigmoid(dec_row . Wfcw + bfcw)
    const float* drow = dec + (size_t)bq * D;
    float pw = drow[t]*Wfcw[t] + drow[t+256]*Wfcw[t+256];
#pragma unroll
    for (int o = 16; o > 0; o >>= 1) pw += __shfl_xor_sync(0xFFFFFFFFu, pw, o);
    if (lane == 0) sred[h] = pw;
    __syncthreads();                      // also fences the gsum atomics
    float wsum = sred[0];
#pragma unroll
    for (int i = 1; i < 8; i++) wsum += sred[i];
    const float w = 1.0f / (1.0f + __expf(-(wsum + bfcw[0])));

    // Z = (VOCAB - G) + sum_g exp(s_g)
    const int G = g_ng[b];
    float pz = 0.f;
    for (int g = t; g < G; g += 256){ float e = __expf(gsum[g]); gsum[g] = e; pz += e; }
#pragma unroll
    for (int o = 16; o > 0; o >>= 1) pz += __shfl_xor_sync(0xFFFFFFFFu, pz, o);
    if (lane == 0) sred[8 + h] = pz;
    __syncthreads();
    float zs = sred[8];
#pragma unroll
    for (int i = 9; i < 16; i++) zs += sred[i];
    const float Z = (float)(VOCABSZ - G) + zs;
    const float wz = w / Z;

    if (t == 0){ g_wz[bq] = wz; g_cw[bq] = 1.0f - w; }
    float* gv = g_gval + (size_t)bq * TS;
    for (int g = t; g < G; g += 256) gv[g] = wz * gsum[g];
}

// final stream with inline bitmap fixups + streaming cache hints
__global__ void k_final(const float* __restrict__ p1, float* __restrict__ out){
    const int bq = blockIdx.x, b = bq >> 9;
    const int t = threadIdx.x;
    __shared__ unsigned sbmp[NBMPW];
    for (int i = t; i < NBMPW; i += 512) sbmp[i] = g_bmp[b*NBMPW + i];
    const float wz = g_wz[bq], cw = g_cw[bq];
    __syncthreads();

    const float4* p14 = (const float4*)(p1 + (size_t)bq * VOCABSZ);
    float4* o4 = (float4*)(out + (size_t)bq * VOCABSZ);
    const int* tmap = g_tokmap + (size_t)b * VOCABSZ;
    const float* gval = g_gval + (size_t)bq * TS;

#pragma unroll 4
    for (int i = t; i < VOCABSZ/4; i += 512){
        float4 v = __ldcs(&p14[i]);
        unsigned bits = (sbmp[i >> 3] >> ((i & 7) * 4)) & 0xFu;
        float4 r;
        r.x = fmaf(cw, v.x, wz); r.y = fmaf(cw, v.y, wz);
        r.z = fmaf(cw, v.z, wz); r.w = fmaf(cw, v.w, wz);
        if (bits){
            const int v0 = i * 4;
            if (bits & 1u) r.x = gval[tmap[v0+0]] + cw*v.x;
            if (bits & 2u) r.y = gval[tmap[v0+1]] + cw*v.y;
            if (bits & 4u) r.z = gval[tmap[v0+2]] + cw*v.z;
            if (bits & 8u) r.w = gval[tmap[v0+3]] + cw*v.w;
        }
        __stcs(&o4[i], r);
    }
}

// ---------------- launch ----------------
extern "C" void kernel_launch(void* const* d_in, const int* in_sizes, int n_in,
                              void* d_out, int out_size){
    int off = (in_sizes[0] == 1) ? 1 : 0;
    const float* dec  = (const float*)d_in[off + 0];
    const float* enc  = (const float*)d_in[off + 1];
    const int*   src  = (const int*)  d_in[off + 2];
    const float* p1   = (const float*)d_in[off + 3];
    const float* WfcQ = (const float*)d_in[off + 4];
    const float* bfcQ = (const float*)d_in[off + 5];
    const float* Wq   = (const float*)d_in[off + 6];
    const float* bq   = (const float*)d_in[off + 7];
    const float* Wk   = (const float*)d_in[off + 8];
    const float* bk   = (const float*)d_in[off + 9];
    const float* Wfcw = (const float*)d_in[off + 10];
    const float* bfcw = (const float*)d_in[off + 11];
    float* out = (float*)d_out;

    k_prep    <<<PREP_TOTAL, 256>>>(src, Wq, bfcQ, bq, WfcQ, dec, enc, Wk);
    k_proj_h  <<<dim3(4,16,2), 256>>>(bk);
    k_scores_h<<<dim3(4,4,32), 256>>>();
    k_attn    <<<ROWS, 256>>>(dec, Wfcw, bfcw);
    k_final   <<<ROWS, 512>>>(p1, out);
}

// round 10
// speedup vs baseline: 2.3537x; 1.1943x over previous
#include <cuda_runtime.h>
#include <cuda_bf16.h>
#include <cstdint>

#define D       512
#define HEADS   8
#define DH      64
#define NB      4
#define TQ      512
#define TS      512
#define VOCABSZ 32000
#define ROWS    (NB*TQ)          // 2048
#define NBMPW   (VOCABSZ/32)     // 1000 bitmap words per batch

typedef unsigned long long ull;

// ---------------- scratch ----------------
__device__ float g_bc[D];
__device__ __nv_bfloat16 g_WcB[D*D];
__device__ __nv_bfloat16 g_WkB[D*D];
__device__ __nv_bfloat16 g_decB[ROWS*D];
__device__ __nv_bfloat16 g_encB[ROWS*D];
__device__ __nv_bfloat16 g_QKB[2*ROWS*D];
__device__ __nv_bfloat16 g_scoresB[NB*HEADS*TQ*TS];  // 16.8 MB
__device__ int   g_gid[NB*TS];
__device__ int   g_ng[NB];
__device__ int   g_tokmap[NB*VOCABSZ];
__device__ unsigned g_bmp[NB*NBMPW];

// ---------------- f32x2 helpers ----------------
__device__ __forceinline__ ull pack2s(float x){
    ull r; asm("mov.b64 %0, {%1, %1};" : "=l"(r) : "r"(__float_as_uint(x))); return r;
}
__device__ __forceinline__ ull pack2f(float x, float y){
    ull r; asm("mov.b64 %0, {%1, %2};" : "=l"(r) : "r"(__float_as_uint(x)), "r"(__float_as_uint(y))); return r;
}
__device__ __forceinline__ void ffma2(ull& d, ull a, ull b){
    asm("fma.rn.f32x2 %0, %1, %2, %0;" : "+l"(d) : "l"(a), "l"(b));
}
__device__ __forceinline__ float2 unpack2(ull v){
    unsigned lo, hi; asm("mov.b64 {%0, %1}, %2;" : "=r"(lo), "=r"(hi) : "l"(v));
    return make_float2(__uint_as_float(lo), __uint_as_float(hi));
}

// ---------------- HMMA / cp.async helpers ----------------
__device__ __forceinline__ uint32_t smem_u32(const void* p){
    uint32_t a;
    asm("{ .reg .u64 t; cvta.to.shared.u64 t, %1; cvt.u32.u64 %0, t; }" : "=r"(a) : "l"(p));
    return a;
}
__device__ __forceinline__ void ldm_x4(uint32_t addr, uint32_t& r0, uint32_t& r1,
                                       uint32_t& r2, uint32_t& r3){
    asm volatile("ldmatrix.sync.aligned.m8n8.x4.shared.b16 {%0,%1,%2,%3}, [%4];"
        : "=r"(r0), "=r"(r1), "=r"(r2), "=r"(r3) : "r"(addr));
}
__device__ __forceinline__ void mma_bf16(float* c, uint32_t a0, uint32_t a1, uint32_t a2,
                                         uint32_t a3, uint32_t b0, uint32_t b1){
    asm volatile("mma.sync.aligned.m16n8k16.row.col.f32.bf16.bf16.f32 "
        "{%0,%1,%2,%3}, {%4,%5,%6,%7}, {%8,%9}, {%0,%1,%2,%3};"
        : "+f"(c[0]), "+f"(c[1]), "+f"(c[2]), "+f"(c[3])
        : "r"(a0), "r"(a1), "r"(a2), "r"(a3), "r"(b0), "r"(b1));
}
__device__ __forceinline__ void cp16(uint32_t dst, const void* src){
    asm volatile("cp.async.cg.shared.global [%0], [%1], 16;" :: "r"(dst), "l"(src));
}
#define CP_COMMIT() asm volatile("cp.async.commit_group;" ::: "memory")
#define CP_WAIT(n)  asm volatile("cp.async.wait_group %0;" :: "n"(n) : "memory")

// ---- 128x128-tile NT GEMM on HMMA, cp.async double-buffered ----
template<int NCHUNK, bool OUT_BF16, bool BIAS>
__device__ __forceinline__ void hgemm_nt(
    const __nv_bfloat16* __restrict__ A, const __nv_bfloat16* __restrict__ B,
    void* __restrict__ Cout, int ldc, const float* __restrict__ bias,
    float alpha, int m0, int n0)
{
    __shared__ __align__(16) uint8_t sm[2*32768];
    const int tid = threadIdx.x;
    const int w = tid >> 5, lane = tid & 31;
    const int wm = w >> 2, wn = w & 3;
    const uint32_t sbase = smem_u32(sm);

    float acc[4][4][4];
#pragma unroll
    for (int i=0;i<4;i++)
#pragma unroll
        for (int j=0;j<4;j++)
#pragma unroll
            for (int k=0;k<4;k++) acc[i][j][k] = 0.f;

    auto issue = [&](int c, int bsel){
        const uint32_t dstA = sbase + bsel*32768;
        const uint32_t dstB = dstA + 16384;
#pragma unroll
        for (int it = 0; it < 4; it++){
            const int i = tid + it*256;
            const int r = i >> 3, cb = i & 7;
            const int sw = (cb ^ (r & 7)) << 4;
            cp16(dstA + r*128 + sw, A + (size_t)(m0 + r)*512 + c*64 + cb*8);
            cp16(dstB + r*128 + sw, B + (size_t)(n0 + r)*512 + c*64 + cb*8);
        }
        CP_COMMIT();
    };

    issue(0, 0);
    if (NCHUNK > 1) issue(1, 1);

    const int rowA_l = (lane & 7) + ((lane >> 3) & 1) * 8;
    const int kbA_l  = lane >> 4;
    const int rowB_l = (lane & 7) + ((lane >> 4) & 1) * 8;
    const int kbB_l  = (lane >> 3) & 1;

#pragma unroll
    for (int c = 0; c < NCHUNK; c++){
        if (c + 1 < NCHUNK) { CP_WAIT(1); } else { CP_WAIT(0); }
        __syncthreads();
        const uint32_t sA = sbase + (c & 1)*32768;
        const uint32_t sB = sA + 16384;
#pragma unroll
        for (int ks = 0; ks < 4; ks++){
            uint32_t af[4][4];
#pragma unroll
            for (int fm = 0; fm < 4; fm++){
                const int row = wm*64 + fm*16 + rowA_l;
                const int kb  = ks*2 + kbA_l;
                ldm_x4(sA + row*128 + ((kb ^ (row & 7)) << 4),
                       af[fm][0], af[fm][1], af[fm][2], af[fm][3]);
            }
            uint32_t bf[2][4];
#pragma unroll
            for (int fn = 0; fn < 2; fn++){
                const int row = wn*32 + fn*16 + rowB_l;
                const int kb  = ks*2 + kbB_l;
                ldm_x4(sB + row*128 + ((kb ^ (row & 7)) << 4),
                       bf[fn][0], bf[fn][1], bf[fn][2], bf[fn][3]);
            }
#pragma unroll
            for (int fm = 0; fm < 4; fm++)
#pragma unroll
                for (int j = 0; j < 4; j++)
                    mma_bf16(acc[fm][j], af[fm][0], af[fm][1], af[fm][2], af[fm][3],
                             bf[j>>1][(j&1)*2], bf[j>>1][(j&1)*2 + 1]);
        }
        __syncthreads();
        if (c + 2 < NCHUNK) issue(c + 2, c & 1);
    }

    const int r_l = lane >> 2, c_l = (lane & 3) * 2;
#pragma unroll
    for (int fm = 0; fm < 4; fm++){
#pragma unroll
        for (int j = 0; j < 4; j++){
            const int row = m0 + wm*64 + fm*16 + r_l;
            const int col = n0 + wn*32 + (j>>1)*16 + (j&1)*8 + c_l;
            const float* a = acc[fm][j];
            float b0 = 0.f, b1 = 0.f;
            if (BIAS){ b0 = bias[col]; b1 = bias[col+1]; }
            if (OUT_BF16){
                __nv_bfloat16* O = (__nv_bfloat16*)Cout;
                *(__nv_bfloat162*)(O + (size_t)row*ldc + col) =
                    __floats2bfloat162_rn((a[0]+b0)*alpha, (a[1]+b1)*alpha);
                *(__nv_bfloat162*)(O + (size_t)(row+8)*ldc + col) =
                    __floats2bfloat162_rn((a[2]+b0)*alpha, (a[3]+b1)*alpha);
            } else {
                float* O = (float*)Cout;
                *(float2*)(O + (size_t)row*ldc + col) = make_float2((a[0]+b0)*alpha, (a[1]+b1)*alpha);
                *(float2*)(O + (size_t)(row+8)*ldc + col) = make_float2((a[2]+b0)*alpha, (a[3]+b1)*alpha);
            }
        }
    }
}

__global__ void __launch_bounds__(256) k_proj_h(const float* __restrict__ bk){
    if (blockIdx.z == 0)
        hgemm_nt<8,true,true>(g_decB, g_WcB, g_QKB, 512, g_bc, 0.125f,
                              blockIdx.y*128, blockIdx.x*128);
    else
        hgemm_nt<8,true,true>(g_encB, g_WkB, g_QKB + (size_t)ROWS*D, 512, bk, 1.0f,
                              blockIdx.y*128, blockIdx.x*128);
}

__global__ void __launch_bounds__(256) k_scores_h(){
    const int z = blockIdx.z, b = z >> 3, h = z & 7;
    hgemm_nt<1,true,false>(g_QKB + (size_t)(b*TQ)*D + h*DH,
                           g_QKB + (size_t)(ROWS + b*TS)*D + h*DH,
                           g_scoresB + (size_t)z*TQ*TS, TS, nullptr, 1.0f,
                           blockIdx.y*128, blockIdx.x*128);
}

// ---------------- merged prep kernel ----------------
// blocks [0,4): grouping ; [4,20): bc ; [20,276): fold ; [276,2580): fp32->bf16
#define PREP_GRP_END 4
#define PREP_BC_END  20
#define PREP_FOLD_END 276
#define PREP_TOTAL   (PREP_FOLD_END + 2304)   // 2580

__global__ void k_prep(const int* __restrict__ src,
                       const float* __restrict__ Wq, const float* __restrict__ bfcQ,
                       const float* __restrict__ bq, const float* __restrict__ WfcQ,
                       const float* __restrict__ dec, const float* __restrict__ enc,
                       const float* __restrict__ Wk){
    __shared__ __align__(16) int shraw[4656];   // 18.6 KB
    const int blk = blockIdx.x, t = threadIdx.x;
    const int lane = t & 31, w = t >> 5;

    if (blk < PREP_GRP_END){
        const int b = blk;
        int* stok   = shraw;            // 512
        int* sfirst = shraw + 512;      // 512
        int* sgarr  = shraw + 1024;     // 512
        int* hkey   = shraw + 1536;     // 1024
        int* hval   = shraw + 2560;     // 1024
        unsigned* sbmp = (unsigned*)(shraw + 3584); // 1000
        int* swcnt  = shraw + 4584;     // 16
        int* swbase = shraw + 4600;     // 16

        stok[t]     = src[b*TS + t];
        stok[t+256] = src[b*TS + t + 256];
        for (int i = t; i < 1024; i += 256){ hkey[i] = -1; hval[i] = 0x7fffffff; }
        for (int i = t; i < NBMPW; i += 256) sbmp[i] = 0u;
        __syncthreads();

        // hash-insert both elements; record slot in sfirst temporarily
#pragma unroll
        for (int half = 0; half < 2; half++){
            const int jj = t + half*256;
            const int tok = stok[jj];
            int slot = (int)(((unsigned)tok * 2654435761u) >> 22);
            while (true){
                int k = atomicCAS(&hkey[slot], -1, tok);
                if (k == -1 || k == tok) break;
                slot = (slot + 1) & 1023;
            }
            atomicMin(&hval[slot], jj);
            sfirst[jj] = slot;
        }
        __syncthreads();
        // resolve first occurrence index
        const int f0 = hval[sfirst[t]];
        const int f1 = hval[sfirst[t+256]];
        sfirst[t] = f0; sfirst[t+256] = f1;

        // ballot scan over "is first" flags (order: elements 0..255 then 256..511)
        const unsigned ltm = (1u << lane) - 1u;
        const unsigned m0 = __ballot_sync(0xFFFFFFFFu, f0 == t);
        const unsigned m1 = __ballot_sync(0xFFFFFFFFu, f1 == t + 256);
        if (lane == 0){ swcnt[w] = __popc(m0); swcnt[8 + w] = __popc(m1); }
        __syncthreads();
        if (t == 0){
            int run = 0;
#pragma unroll
            for (int i = 0; i < 16; i++){ swbase[i] = run; run += swcnt[i]; }
            g_ng[b] = run;
        }
        __syncthreads();
        sgarr[t]       = swbase[w]     + __popc(m0 & ltm);
        sgarr[t + 256] = swbase[8 + w] + __popc(m1 & ltm);
        __syncthreads();

#pragma unroll
        for (int half = 0; half < 2; half++){
            const int jj = t + half*256;
            const int f = sfirst[jj];
            const int g = sgarr[f];
            g_gid[b*TS + jj] = g;
            if (f == jj){
                const int tok = stok[jj];
                g_tokmap[b*VOCABSZ + tok] = g;
                atomicOr(&sbmp[tok >> 5], 1u << (tok & 31));
            }
        }
        __syncthreads();
        for (int i = t; i < NBMPW; i += 256) g_bmp[b*NBMPW + i] = sbmp[i];
    } else if (blk < PREP_BC_END){
        const int row = (blk - PREP_GRP_END)*32 + (t >> 3);
        const int l8 = t & 7;
        float s = 0.f;
        for (int k = l8; k < D; k += 8) s += Wq[(size_t)row*D + k] * bfcQ[k];
        s += __shfl_down_sync(0xFFFFFFFFu, s, 4, 8);
        s += __shfl_down_sync(0xFFFFFFFFu, s, 2, 8);
        s += __shfl_down_sync(0xFFFFFFFFu, s, 1, 8);
        if (l8 == 0) g_bc[row] = s + bq[row];
    } else if (blk < PREP_FOLD_END){
        // fold: Wc = Wq @ WfcQ (NN), bf16 out. 32x32 tiles.
        const int idx = blk - PREP_BC_END;
        const int m0 = (idx >> 4)*32, n0 = (idx & 15)*32;
        float (*As)[34] = (float(*)[34])shraw;
        float (*Bs)[34] = (float(*)[34])((char*)shraw + 4352);
        const int tx = t & 15, ty = t >> 4;
        ull acc0 = 0ULL, acc1 = 0ULL;
        const int lrow = t >> 3, lc4 = t & 7;
        for (int c0 = 0; c0 < D; c0 += 32){
            float4 av = *(const float4*)(Wq   + (size_t)(m0 + lrow)*D + c0 + lc4*4);
            float4 bv = *(const float4*)(WfcQ + (size_t)(c0 + lrow)*D + n0 + lc4*4);
            __syncthreads();
            const int kb = lc4*4;
            As[kb+0][lrow]=av.x; As[kb+1][lrow]=av.y; As[kb+2][lrow]=av.z; As[kb+3][lrow]=av.w;
            Bs[lrow][kb+0]=bv.x; Bs[lrow][kb+1]=bv.y; Bs[lrow][kb+2]=bv.z; Bs[lrow][kb+3]=bv.w;
            __syncthreads();
#pragma unroll
            for (int kk = 0; kk < 32; kk++){
                float2 a = *(const float2*)&As[kk][ty*2];
                float2 b = *(const float2*)&Bs[kk][tx*2];
                ull ap = pack2f(a.x, a.y);
                ffma2(acc0, ap, pack2s(b.x));
                ffma2(acc1, ap, pack2s(b.y));
            }
        }
        float2 u0 = unpack2(acc0), u1 = unpack2(acc1);
        const int r0 = m0 + ty*2, cc = n0 + tx*2;
        *(__nv_bfloat162*)(g_WcB + (size_t)r0*D + cc)     = __floats2bfloat162_rn(u0.x, u1.x);
        *(__nv_bfloat162*)(g_WcB + (size_t)(r0+1)*D + cc) = __floats2bfloat162_rn(u0.y, u1.y);
    } else {
        const int n1 = ROWS*D;
        const int i4 = ((blk - PREP_FOLD_END)*256 + t) * 4;
        const float* s; __nv_bfloat16* d;
        if (i4 < n1){ s = dec + i4; d = g_decB + i4; }
        else if (i4 < 2*n1){ s = enc + (i4 - n1); d = g_encB + (i4 - n1); }
        else { s = Wk + (i4 - 2*n1); d = g_WkB + (i4 - 2*n1); }
        float4 v = *(const float4*)s;
        *(__nv_bfloat162*)d       = __floats2bfloat162_rn(v.x, v.y);
        *(__nv_bfloat162*)(d + 2) = __floats2bfloat162_rn(v.z, v.w);
    }
}

// ---------------- fused attention-combine + output stream ----------------
// grid 2048 (b,q), 512 threads = 16 warps.
__global__ void __launch_bounds__(512) k_attn_final(
    const float* __restrict__ dec, const float* __restrict__ Wfcw,
    const float* __restrict__ bfcw, const float* __restrict__ p1,
    float* __restrict__ out){
    const int bq = blockIdx.x, b = bq >> 9, q = bq & 511;
    const int t = threadIdx.x, lane = t & 31, w = t >> 5;
    __shared__ float sattn[HEADS][512];
    __shared__ float gsum[512];
    __shared__ float sinv[HEADS];
    __shared__ float sredg[8];
    __shared__ float sredz[16];
    __shared__ unsigned sbmp[NBMPW];
    gsum[t] = 0.f;

    if (w < 8){
        // warp w = head w: softmax numerators over full ts row
        const int h = w;
        const uint2* rp = (const uint2*)(g_scoresB + ((size_t)(b*HEADS + h)*TQ + q) * TS);
        float4 ev[4];
        float m = -1e30f;
#pragma unroll
        for (int j = 0; j < 4; j++){
            const uint2 u = rp[lane + 32*j];
            const __nv_bfloat162 p0 = *(const __nv_bfloat162*)&u.x;
            const __nv_bfloat162 pq = *(const __nv_bfloat162*)&u.y;
            float4 v = make_float4(__bfloat162float(p0.x), __bfloat162float(p0.y),
                                   __bfloat162float(pq.x), __bfloat162float(pq.y));
            ev[j] = v;
            m = fmaxf(m, fmaxf(fmaxf(v.x, v.y), fmaxf(v.z, v.w)));
        }
#pragma unroll
        for (int o = 16; o > 0; o >>= 1) m = fmaxf(m, __shfl_xor_sync(0xFFFFFFFFu, m, o));
        float s = 0.f;
#pragma unroll
        for (int j = 0; j < 4; j++){
            ev[j].x = __expf(ev[j].x - m); ev[j].y = __expf(ev[j].y - m);
            ev[j].z = __expf(ev[j].z - m); ev[j].w = __expf(ev[j].w - m);
            s += ev[j].x + ev[j].y + ev[j].z + ev[j].w;
        }
#pragma unroll
        for (int o = 16; o > 0; o >>= 1) s += __shfl_xor_sync(0xFFFFFFFFu, s, o);
        if (lane == 0) sinv[h] = 1.0f / (8.0f * s);
#pragma unroll
        for (int j = 0; j < 4; j++)
            *(float4*)&sattn[h][(lane + 32*j)*4] = ev[j];
    } else {
        // warps 8..15: bitmap load + gate partials
        const int t2 = t - 256;                 // 0..255
        for (int i = t2; i < NBMPW; i += 256) sbmp[i] = g_bmp[b*NBMPW + i];
        const float* drow = dec + (size_t)bq * D;
        float pw = drow[t2]*Wfcw[t2] + drow[t2+256]*Wfcw[t2+256];
#pragma unroll
        for (int o = 16; o > 0; o >>= 1) pw += __shfl_xor_sync(0xFFFFFFFFu, pw, o);
        if (lane == 0) sredg[w - 8] = pw;
    }
    __syncthreads();

    // head combine + group scatter (512 threads, 1 element each)
    {
        float a = 0.f;
#pragma unroll
        for (int hh = 0; hh < HEADS; hh++) a += sattn[hh][t] * sinv[hh];
        atomicAdd(&gsum[g_gid[b*TS + t]], a);
    }
    __syncthreads();

    float wsum = sredg[0];
#pragma unroll
    for (int i = 1; i < 8; i++) wsum += sredg[i];
    const float wgate = 1.0f / (1.0f + __expf(-(wsum + bfcw[0])));

    // Z over groups
    const int G = g_ng[b];
    float pz = 0.f;
    if (t < G){ float e = __expf(gsum[t]); gsum[t] = e; pz += e; }
#pragma unroll
    for (int o = 16; o > 0; o >>= 1) pz += __shfl_xor_sync(0xFFFFFFFFu, pz, o);
    if (lane == 0) sredz[w] = pz;
    __syncthreads();
    float zs = sredz[0];
#pragma unroll
    for (int i = 1; i < 16; i++) zs += sredz[i];
    const float Z = (float)(VOCABSZ - G) + zs;
    const float wz = wgate / Z;
    const float cw = 1.0f - wgate;

    // HBM stream with inline bitmap fixups
    const float4* p14 = (const float4*)(p1 + (size_t)bq * VOCABSZ);
    float4* o4 = (float4*)(out + (size_t)bq * VOCABSZ);
    const int* tmap = g_tokmap + (size_t)b * VOCABSZ;

#pragma unroll 4
    for (int i = t; i < VOCABSZ/4; i += 512){
        float4 v = __ldcs(&p14[i]);
        unsigned bits = (sbmp[i >> 3] >> ((i & 7) * 4)) & 0xFu;
        float4 r;
        r.x = fmaf(cw, v.x, wz); r.y = fmaf(cw, v.y, wz);
        r.z = fmaf(cw, v.z, wz); r.w = fmaf(cw, v.w, wz);
        if (bits){
            const int v0 = i * 4;
            if (bits & 1u) r.x = wz * gsum[tmap[v0+0]] + cw*v.x;
            if (bits & 2u) r.y = wz * gsum[tmap[v0+1]] + cw*v.y;
            if (bits & 4u) r.z = wz * gsum[tmap[v0+2]] + cw*v.z;
            if (bits & 8u) r.w = wz * gsum[tmap[v0+3]] + cw*v.w;
        }
        __stcs(&o4[i], r);
    }
}

// ---------------- launch ----------------
extern "C" void kernel_launch(void* const* d_in, const int* in_sizes, int n_in,
                              void* d_out, int out_size){
    int off = (in_sizes[0] == 1) ? 1 : 0;
    const float* dec  = (const float*)d_in[off + 0];
    const float* enc  = (const float*)d_in[off + 1];
    const int*   src  = (const int*)  d_in[off + 2];
    const float* p1   = (const float*)d_in[off + 3];
    const float* WfcQ = (const float*)d_in[off + 4];
    const float* bfcQ = (const float*)d_in[off + 5];
    const float* Wq   = (const float*)d_in[off + 6];
    const float* bq   = (const float*)d_in[off + 7];
    const float* Wk   = (const float*)d_in[off + 8];
    const float* bk   = (const float*)d_in[off + 9];
    const float* Wfcw = (const float*)d_in[off + 10];
    const float* bfcw = (const float*)d_in[off + 11];
    float* out = (float*)d_out;

    k_prep      <<<PREP_TOTAL, 256>>>(src, Wq, bfcQ, bq, WfcQ, dec, enc, Wk);
    k_proj_h    <<<dim3(4,16,2), 256>>>(bk);
    k_scores_h  <<<dim3(4,4,32), 256>>>();
    k_attn_final<<<ROWS, 512>>>(dec, Wfcw, bfcw, p1, out);
}